// round 10
// baseline (speedup 1.0000x reference)
#include <cuda_runtime.h>
#include <cuda_bf16.h>
#include <mma.h>
#include <math.h>
#include <stdint.h>

using namespace nvcuda;

// ---------------- problem constants ----------------
#define BATCH 8192
#define DIM   2048
#define NE    8
#define NG    4
#define PP    512
#define HH    192
#define CAP   17408          // max padded assignments (128-row tiles)
#define MTILES 136           // CAP/128
#define KCH   16             // K elems per smem chunk (2-stage double buffer)

// ---------------- device scratch (~36 MB total — proven-safe envelope) ----------------
__device__ int   g_count[NE];
__device__ int   g_cursor[NE];
__device__ int   g_padOff[NE + 1];
__device__ int   g_Mtot;
__device__ int   g_routeE[2 * BATCH];
__device__ float g_routeW[2 * BATCH];
__device__ __align__(1024) int   g_assignRow[CAP];
__device__ __align__(1024) float g_assignW[CAP];
__device__ __align__(1024) __nv_bfloat16 g_Hhi[(size_t)CAP * PP];
__device__ __align__(1024) __nv_bfloat16 g_Hlo[(size_t)CAP * PP];

// ---------------- smem layout ----------------
#define STAGE_SZ 16896
#define SAH(s) ((s) * STAGE_SZ)
#define SAL(s) ((s) * STAGE_SZ + 6144)
#define SBH(s) ((s) * STAGE_SZ + 12288)
#define SBL(s) ((s) * STAGE_SZ + 14592)
#define CBUF_LD 68
#define SMEM_BYTES 34816

// ---------------- init: zero output + scratch ----------------
__global__ __launch_bounds__(256) void init_kernel(float4* __restrict__ out4) {
    int i = blockIdx.x * 256 + threadIdx.x;           // 16384 x 256 = BATCH*DIM/4
    if (i < (BATCH * DIM) / 4) out4[i] = make_float4(0.f, 0.f, 0.f, 0.f);
    if (i < CAP) { g_assignRow[i] = -1; g_assignW[i] = 0.f; }
    if (i < NE)  { g_count[i] = 0; g_cursor[i] = 0; }
}

// ---------------- routing (exactness-critical; identical to passing rounds) ----------------
__global__ __launch_bounds__(1024) void route_kernel(
    const float* __restrict__ x,
    const float* __restrict__ Wg, const float* __restrict__ bg,
    const float* __restrict__ Wp, const float* __restrict__ bp,
    const float* __restrict__ Wgg, const float* __restrict__ bgg)
{
    __shared__ float  warpSum[32];
    __shared__ double dWarp[32];
    __shared__ float  sh_qm;
    int b = blockIdx.x, tid = threadIdx.x;

    const float2* xr = (const float2*)(x + (size_t)b * DIM);
    float2 v = xr[tid];
    float acc = v.x + v.y;
    #pragma unroll
    for (int o = 16; o; o >>= 1) acc += __shfl_down_sync(0xffffffffu, acc, o);
    if ((tid & 31) == 0) warpSum[tid >> 5] = acc;
    __syncthreads();
    if (tid < 32) {
        float a2 = warpSum[tid];
        #pragma unroll
        for (int o = 16; o; o >>= 1) a2 += __shfl_down_sync(0xffffffffu, a2, o);
        if (tid == 0) sh_qm = a2 * (1.0f / 2048.0f);
    }
    __syncthreads();
    float qm = sh_qm;

    double tr = 0.0;
    if (tid < HH) {
        float ang = __fmul_rn(qm, (float)(7 * (tid + 1)));
        double da = (double)ang;
        tr = cos(da) + sin(da);
    }
    #pragma unroll
    for (int o = 16; o; o >>= 1) tr += __shfl_down_sync(0xffffffffu, tr, o);
    if ((tid & 31) == 0) dWarp[tid >> 5] = tr;
    __syncthreads();

    if (tid == 0) {
        double t = 0.0;
        #pragma unroll
        for (int i = 0; i < 32; i++) t += dWarp[i];
        double m = t / 384.0;
        const double c = 0.015625;   // KTOP/D: LIF spike rate is exactly constant

        double l[NE]; double mx = -1e300;
        #pragma unroll
        for (int e = 0; e < NE; e++) {
            int g = e & (NG - 1);
            double v2 = (m * (double)Wg[e] + c * (double)Wg[NE + e] + (double)bg[e])
                      - 0.1 * (m * (double)Wp[e] + c * (double)Wp[NE + e] + (double)bp[e])
                      + (m * (double)Wgg[g] + c * (double)Wgg[NG + g] + (double)bgg[g]);
            l[e] = v2; mx = fmax(mx, v2);
        }
        double sf[NE], Z = 0.0;
        #pragma unroll
        for (int e = 0; e < NE; e++) { sf[e] = exp(l[e] - mx); Z += sf[e]; }
        int e0 = 0;
        #pragma unroll
        for (int e = 1; e < NE; e++) if (sf[e] > sf[e0]) e0 = e;
        int e1 = (e0 == 0) ? 1 : 0;
        #pragma unroll
        for (int e = 0; e < NE; e++) if (e != e0 && sf[e] > sf[e1]) e1 = e;
        double s0 = sf[e0] / Z, s1 = sf[e1] / Z;
        double den = s0 + s1 + 1e-9;

        g_routeE[2 * b] = e0; g_routeE[2 * b + 1] = e1;
        g_routeW[2 * b] = (float)(s0 / den); g_routeW[2 * b + 1] = (float)(s1 / den);
        atomicAdd(&g_count[e0], 1);
        atomicAdd(&g_count[e1], 1);
    }
}

// ---------------- scatter (computes prefix locally; replaces scan_kernel) ----------------
__global__ __launch_bounds__(128) void scatter_kernel() {
    int b = blockIdx.x * 128 + threadIdx.x;
    int off[NE + 1];
    off[0] = 0;
    #pragma unroll
    for (int e = 0; e < NE; e++)
        off[e + 1] = off[e] + ((g_count[e] + 127) & ~127);
    if (b == 0) {
        #pragma unroll
        for (int e = 0; e <= NE; e++) g_padOff[e] = off[e];
        g_Mtot = off[NE];
    }
    if (b >= BATCH) return;
    #pragma unroll
    for (int j = 0; j < 2; j++) {
        int e = g_routeE[2 * b + j];
        int pos = off[e] + atomicAdd(&g_cursor[e], 1);
        g_assignRow[pos] = b;
        g_assignW[pos]   = g_routeW[2 * b + j];
    }
}

// ---------------- helpers ----------------
__device__ __forceinline__ void split4(float4 v, uint2& hi, uint2& lo) {
    __nv_bfloat162 h01 = __floats2bfloat162_rn(v.x, v.y);
    __nv_bfloat162 h23 = __floats2bfloat162_rn(v.z, v.w);
    hi.x = *(uint32_t*)&h01;
    hi.y = *(uint32_t*)&h23;
    __nv_bfloat162 l01 = __floats2bfloat162_rn(v.x - __bfloat162float(h01.x),
                                               v.y - __bfloat162float(h01.y));
    __nv_bfloat162 l23 = __floats2bfloat162_rn(v.z - __bfloat162float(h23.x),
                                               v.w - __bfloat162float(h23.y));
    lo.x = *(uint32_t*)&l01;
    lo.y = *(uint32_t*)&l23;
}

// =====================================================================
// WMMA GEMM: CTA tile 128x64, 8 warps (warp 32x32 = 2x2 wmma16x16x16),
// KCH=16, 2-stage smem double buffer + 2-deep register prefetch,
// split-3 bf16 (hh + hl + lh), fp32 accumulate.
// =====================================================================

// ---------------- GEMM1: H = relu(X[rows] @ W1[e] + b1[e]); W1 is [k][n] ----------------
__global__ __launch_bounds__(256, 2) void wmma_gemm1(
    const float* __restrict__ x, const float* __restrict__ W1, const float* __restrict__ b1)
{
    __shared__ __align__(16) char smem[SMEM_BYTES];
    __shared__ int s_row[128];

    int m0 = blockIdx.y * 128;
    if (m0 >= g_Mtot) return;
    int e = 0;
    #pragma unroll
    for (int i = 1; i < NE; i++) if (m0 >= g_padOff[i]) e = i;
    int n0 = blockIdx.x * 64;
    int tid = threadIdx.x, wid = tid >> 5;
    int wm = wid & 3, wn = wid >> 2;

    if (tid < 128) { int r = g_assignRow[m0 + tid]; s_row[tid] = r < 0 ? 0 : r; }
    __syncthreads();

    const float* Wb = W1 + (size_t)e * DIM * PP;

    int arow = tid >> 2, aq = tid & 3;
    int brow = tid >> 4, bq = tid & 15;
    const float* aP0 = x + (size_t)s_row[arow] * DIM + aq * 4;
    const float* aP1 = x + (size_t)s_row[arow + 64] * DIM + aq * 4;
    const float* bP  = Wb + (size_t)brow * PP + n0 + bq * 4;

    // 2-deep register prefetch
    float4 pa0[2], pa1[2], pb[2];
    pa0[0] = *(const float4*)aP0;
    pa1[0] = *(const float4*)aP1;
    pb[0]  = *(const float4*)bP;
    pa0[1] = *(const float4*)(aP0 + KCH);
    pa1[1] = *(const float4*)(aP1 + KCH);
    pb[1]  = *(const float4*)(bP + (size_t)KCH * PP);

    wmma::fragment<wmma::accumulator, 16, 16, 16, float> acc[2][2];
    #pragma unroll
    for (int mi = 0; mi < 2; mi++)
        #pragma unroll
        for (int ni = 0; ni < 2; ni++)
            wmma::fill_fragment(acc[mi][ni], 0.0f);

    const int NK = DIM / KCH;   // 128
    for (int k = 0; k < NK; k++) {
        int s = k & 1;
        __nv_bfloat16* sAhi = (__nv_bfloat16*)(smem + SAH(s));
        __nv_bfloat16* sAlo = (__nv_bfloat16*)(smem + SAL(s));
        __nv_bfloat16* sBhi = (__nv_bfloat16*)(smem + SBH(s));
        __nv_bfloat16* sBlo = (__nv_bfloat16*)(smem + SBL(s));

        {   // STS from prefetched regs (buffer k&1)
            uint2 hi, lo;
            split4(pa0[s], hi, lo);
            *(uint2*)&sAhi[arow * 24 + aq * 4] = hi;
            *(uint2*)&sAlo[arow * 24 + aq * 4] = lo;
            split4(pa1[s], hi, lo);
            *(uint2*)&sAhi[(arow + 64) * 24 + aq * 4] = hi;
            *(uint2*)&sAlo[(arow + 64) * 24 + aq * 4] = lo;
            split4(pb[s], hi, lo);
            *(uint2*)&sBhi[brow * 72 + bq * 4] = hi;
            *(uint2*)&sBlo[brow * 72 + bq * 4] = lo;
        }
        __syncthreads();

        if (k + 2 < NK) {       // refill buffer k&1; consumed at iter k+2
            int k0 = (k + 2) * KCH;
            pa0[s] = *(const float4*)(aP0 + k0);
            pa1[s] = *(const float4*)(aP1 + k0);
            pb[s]  = *(const float4*)(bP + (size_t)k0 * PP);
        }

        wmma::fragment<wmma::matrix_a, 16, 16, 16, __nv_bfloat16, wmma::row_major> ah[2], al[2];
        wmma::fragment<wmma::matrix_b, 16, 16, 16, __nv_bfloat16, wmma::row_major> bh[2], bl[2];
        #pragma unroll
        for (int mi = 0; mi < 2; mi++) {
            wmma::load_matrix_sync(ah[mi], &sAhi[(wm * 32 + mi * 16) * 24], 24);
            wmma::load_matrix_sync(al[mi], &sAlo[(wm * 32 + mi * 16) * 24], 24);
        }
        #pragma unroll
        for (int ni = 0; ni < 2; ni++) {
            wmma::load_matrix_sync(bh[ni], &sBhi[wn * 32 + ni * 16], 72);
            wmma::load_matrix_sync(bl[ni], &sBlo[wn * 32 + ni * 16], 72);
        }
        #pragma unroll
        for (int mi = 0; mi < 2; mi++)
            #pragma unroll
            for (int ni = 0; ni < 2; ni++) {
                wmma::mma_sync(acc[mi][ni], ah[mi], bh[ni], acc[mi][ni]);
                wmma::mma_sync(acc[mi][ni], ah[mi], bl[ni], acc[mi][ni]);
                wmma::mma_sync(acc[mi][ni], al[mi], bh[ni], acc[mi][ni]);
            }
    }
    __syncthreads();

    // epilogue: acc -> smem float buffer -> bias+relu+split -> g_Hhi/Hlo
    float* Cbuf = (float*)smem;
    #pragma unroll
    for (int mi = 0; mi < 2; mi++)
        #pragma unroll
        for (int ni = 0; ni < 2; ni++)
            wmma::store_matrix_sync(&Cbuf[(wm * 32 + mi * 16) * CBUF_LD + wn * 32 + ni * 16],
                                    acc[mi][ni], CBUF_LD, wmma::mem_row_major);
    __syncthreads();

    const float* bb = b1 + e * PP;
    #pragma unroll
    for (int j = 0; j < 16; j++) {
        int idx = tid + 256 * j;                   // 128 rows x 32 col-pairs
        int r = idx >> 5, c = (idx & 31) * 2;
        int col = n0 + c;
        float v0 = fmaxf(Cbuf[r * CBUF_LD + c]     + bb[col],     0.f);
        float v1 = fmaxf(Cbuf[r * CBUF_LD + c + 1] + bb[col + 1], 0.f);
        __nv_bfloat16 h0 = __float2bfloat16_rn(v0), h1 = __float2bfloat16_rn(v1);
        __nv_bfloat162 hh; hh.x = h0; hh.y = h1;
        *(__nv_bfloat162*)&g_Hhi[(size_t)(m0 + r) * PP + col] = hh;
        __nv_bfloat162 ll;
        ll.x = __float2bfloat16_rn(v0 - __bfloat162float(h0));
        ll.y = __float2bfloat16_rn(v1 - __bfloat162float(h1));
        *(__nv_bfloat162*)&g_Hlo[(size_t)(m0 + r) * PP + col] = ll;
    }
}

// ---------------- GEMM2: out[row] += w * (H @ W2[e] + b2[e]); W2 is [k][n] ----------------
__global__ __launch_bounds__(256, 2) void wmma_gemm2(
    const float* __restrict__ W2, const float* __restrict__ b2, float* __restrict__ out)
{
    __shared__ __align__(16) char smem[SMEM_BYTES];
    __shared__ int   s_rowR[128];
    __shared__ float s_w[128];

    int m0 = blockIdx.y * 128;
    if (m0 >= g_Mtot) return;
    int e = 0;
    #pragma unroll
    for (int i = 1; i < NE; i++) if (m0 >= g_padOff[i]) e = i;
    int n0 = blockIdx.x * 64;
    int tid = threadIdx.x, wid = tid >> 5;
    int wm = wid & 3, wn = wid >> 2;

    if (tid < 128) { s_rowR[tid] = g_assignRow[m0 + tid]; s_w[tid] = g_assignW[m0 + tid]; }
    __syncthreads();

    const float* Wb = W2 + (size_t)e * PP * DIM;

    int arow = tid >> 1, aq = tid & 1;
    int brow = tid >> 4, bq = tid & 15;
    const __nv_bfloat16* aPh = g_Hhi + (size_t)(m0 + arow) * PP + aq * 8;
    const __nv_bfloat16* aPl = g_Hlo + (size_t)(m0 + arow) * PP + aq * 8;
    const float* bP = Wb + (size_t)brow * DIM + n0 + bq * 4;

    uint4  prh[2], prl[2];
    float4 pb[2];
    prh[0] = *(const uint4*)aPh;
    prl[0] = *(const uint4*)aPl;
    pb[0]  = *(const float4*)bP;
    prh[1] = *(const uint4*)(aPh + KCH);
    prl[1] = *(const uint4*)(aPl + KCH);
    pb[1]  = *(const float4*)(bP + (size_t)KCH * DIM);

    wmma::fragment<wmma::accumulator, 16, 16, 16, float> acc[2][2];
    #pragma unroll
    for (int mi = 0; mi < 2; mi++)
        #pragma unroll
        for (int ni = 0; ni < 2; ni++)
            wmma::fill_fragment(acc[mi][ni], 0.0f);

    const int NK = PP / KCH;    // 32
    for (int k = 0; k < NK; k++) {
        int s = k & 1;
        __nv_bfloat16* sAhi = (__nv_bfloat16*)(smem + SAH(s));
        __nv_bfloat16* sAlo = (__nv_bfloat16*)(smem + SAL(s));
        __nv_bfloat16* sBhi = (__nv_bfloat16*)(smem + SBH(s));
        __nv_bfloat16* sBlo = (__nv_bfloat16*)(smem + SBL(s));

        {
            *(uint4*)&sAhi[arow * 24 + aq * 8] = prh[s];
            *(uint4*)&sAlo[arow * 24 + aq * 8] = prl[s];
            uint2 hi, lo;
            split4(pb[s], hi, lo);
            *(uint2*)&sBhi[brow * 72 + bq * 4] = hi;
            *(uint2*)&sBlo[brow * 72 + bq * 4] = lo;
        }
        __syncthreads();

        if (k + 2 < NK) {
            int k0 = (k + 2) * KCH;
            prh[s] = *(const uint4*)(aPh + k0);
            prl[s] = *(const uint4*)(aPl + k0);
            pb[s]  = *(const float4*)(bP + (size_t)k0 * DIM);
        }

        wmma::fragment<wmma::matrix_a, 16, 16, 16, __nv_bfloat16, wmma::row_major> ah[2], al[2];
        wmma::fragment<wmma::matrix_b, 16, 16, 16, __nv_bfloat16, wmma::row_major> bh[2], bl[2];
        #pragma unroll
        for (int mi = 0; mi < 2; mi++) {
            wmma::load_matrix_sync(ah[mi], &sAhi[(wm * 32 + mi * 16) * 24], 24);
            wmma::load_matrix_sync(al[mi], &sAlo[(wm * 32 + mi * 16) * 24], 24);
        }
        #pragma unroll
        for (int ni = 0; ni < 2; ni++) {
            wmma::load_matrix_sync(bh[ni], &sBhi[wn * 32 + ni * 16], 72);
            wmma::load_matrix_sync(bl[ni], &sBlo[wn * 32 + ni * 16], 72);
        }
        #pragma unroll
        for (int mi = 0; mi < 2; mi++)
            #pragma unroll
            for (int ni = 0; ni < 2; ni++) {
                wmma::mma_sync(acc[mi][ni], ah[mi], bh[ni], acc[mi][ni]);
                wmma::mma_sync(acc[mi][ni], ah[mi], bl[ni], acc[mi][ni]);
                wmma::mma_sync(acc[mi][ni], al[mi], bh[ni], acc[mi][ni]);
            }
    }
    __syncthreads();

    // epilogue: acc -> smem -> gated atomicAdd into out (2 commutative adds/element)
    float* Cbuf = (float*)smem;
    #pragma unroll
    for (int mi = 0; mi < 2; mi++)
        #pragma unroll
        for (int ni = 0; ni < 2; ni++)
            wmma::store_matrix_sync(&Cbuf[(wm * 32 + mi * 16) * CBUF_LD + wn * 32 + ni * 16],
                                    acc[mi][ni], CBUF_LD, wmma::mem_row_major);
    __syncthreads();

    const float* bb = b2 + e * DIM;
    #pragma unroll
    for (int j = 0; j < 16; j++) {
        int idx = tid + 256 * j;                   // 128 rows x 32 col-pairs
        int r = idx >> 5, c = (idx & 31) * 2;
        int row = s_rowR[r];
        if (row < 0) continue;                     // padding slot
        float w = s_w[r];
        int col = n0 + c;
        float* orow = out + (size_t)row * DIM;
        atomicAdd(&orow[col],     w * (Cbuf[r * CBUF_LD + c]     + bb[col]));
        atomicAdd(&orow[col + 1], w * (Cbuf[r * CBUF_LD + c + 1] + bb[col + 1]));
    }
}

// ---------------- launch ----------------
extern "C" void kernel_launch(void* const* d_in, const int* in_sizes, int n_in,
                              void* d_out, int out_size)
{
    const float* x   = (const float*)d_in[0];
    const float* Wg  = (const float*)d_in[1];
    const float* bg  = (const float*)d_in[2];
    const float* Wp  = (const float*)d_in[3];
    const float* bp  = (const float*)d_in[4];
    const float* Wgg = (const float*)d_in[5];
    const float* bgg = (const float*)d_in[6];
    const float* W1  = (const float*)d_in[7];
    const float* b1  = (const float*)d_in[8];
    const float* W2  = (const float*)d_in[9];
    const float* b2  = (const float*)d_in[10];
    float* out = (float*)d_out;

    init_kernel<<<16384, 256>>>((float4*)out);               // launch 0
    route_kernel<<<BATCH, 1024>>>(x, Wg, bg, Wp, bp, Wgg, bgg); // launch 1
    scatter_kernel<<<(BATCH + 127) / 128, 128>>>();          // launch 2
    wmma_gemm1<<<dim3(PP / 64, MTILES), 256>>>(x, W1, b1);   // launch 3  <- profiled slot
    wmma_gemm2<<<dim3(DIM / 64, MTILES), 256>>>(W2, b2, out);// launch 4
}

// round 11
// speedup vs baseline: 1.7056x; 1.7056x over previous
#include <cuda_runtime.h>
#include <cuda_bf16.h>
#include <cuda_fp16.h>
#include <mma.h>
#include <math.h>
#include <stdint.h>

using namespace nvcuda;

// ---------------- problem constants ----------------
#define BATCH 8192
#define DIM   2048
#define NE    8
#define NG    4
#define PP    512
#define HH    192
#define CAP   18432          // 2*BATCH + 8*255 rounded up to 256-row tiles
#define MT    72             // CAP/256
#define KCH   16             // K elems per smem chunk (2-stage double buffer)

// ---------------- device scratch (~19 MB — well inside proven-safe envelope) ----------------
__device__ int   g_count[NE];
__device__ int   g_cursor[NE];
__device__ int   g_padOff[NE + 1];
__device__ int   g_Mtot;
__device__ int   g_routeE[2 * BATCH];
__device__ float g_routeW[2 * BATCH];
__device__ __align__(1024) int   g_assignRow[CAP];
__device__ __align__(1024) float g_assignW[CAP];
__device__ __align__(1024) __half g_Hh[(size_t)CAP * PP];

// ---------------- smem layout ----------------
// mainloop: sA 2 stages x 256x24 half (12288 B each), sB 2 stages x 16x72 half (2304 B each)
// epilogue (union): Cbuf 128 x 68 fp32 = 34816 B
#define SA(s)  ((s) * 12288)
#define SB(s)  (24576 + (s) * 2304)
#define CBUF_LD 68
#define SMEM_BYTES 34816

// ---------------- init: zero output + scratch ----------------
__global__ __launch_bounds__(256) void init_kernel(float4* __restrict__ out4) {
    int i = blockIdx.x * 256 + threadIdx.x;           // 16384 x 256 = BATCH*DIM/4
    if (i < (BATCH * DIM) / 4) out4[i] = make_float4(0.f, 0.f, 0.f, 0.f);
    if (i < CAP) { g_assignRow[i] = -1; g_assignW[i] = 0.f; }
    if (i < NE)  { g_count[i] = 0; g_cursor[i] = 0; }
}

// ---------------- routing (exactness-critical; identical to passing rounds) ----------------
__global__ __launch_bounds__(1024) void route_kernel(
    const float* __restrict__ x,
    const float* __restrict__ Wg, const float* __restrict__ bg,
    const float* __restrict__ Wp, const float* __restrict__ bp,
    const float* __restrict__ Wgg, const float* __restrict__ bgg)
{
    __shared__ float  warpSum[32];
    __shared__ double dWarp[32];
    __shared__ float  sh_qm;
    int b = blockIdx.x, tid = threadIdx.x;

    const float2* xr = (const float2*)(x + (size_t)b * DIM);
    float2 v = xr[tid];
    float acc = v.x + v.y;
    #pragma unroll
    for (int o = 16; o; o >>= 1) acc += __shfl_down_sync(0xffffffffu, acc, o);
    if ((tid & 31) == 0) warpSum[tid >> 5] = acc;
    __syncthreads();
    if (tid < 32) {
        float a2 = warpSum[tid];
        #pragma unroll
        for (int o = 16; o; o >>= 1) a2 += __shfl_down_sync(0xffffffffu, a2, o);
        if (tid == 0) sh_qm = a2 * (1.0f / 2048.0f);
    }
    __syncthreads();
    float qm = sh_qm;

    double tr = 0.0;
    if (tid < HH) {
        float ang = __fmul_rn(qm, (float)(7 * (tid + 1)));
        double da = (double)ang;
        tr = cos(da) + sin(da);
    }
    #pragma unroll
    for (int o = 16; o; o >>= 1) tr += __shfl_down_sync(0xffffffffu, tr, o);
    if ((tid & 31) == 0) dWarp[tid >> 5] = tr;
    __syncthreads();

    if (tid == 0) {
        double t = 0.0;
        #pragma unroll
        for (int i = 0; i < 32; i++) t += dWarp[i];
        double m = t / 384.0;
        const double c = 0.015625;   // KTOP/D: LIF spike rate is exactly constant

        double l[NE]; double mx = -1e300;
        #pragma unroll
        for (int e = 0; e < NE; e++) {
            int g = e & (NG - 1);
            double v2 = (m * (double)Wg[e] + c * (double)Wg[NE + e] + (double)bg[e])
                      - 0.1 * (m * (double)Wp[e] + c * (double)Wp[NE + e] + (double)bp[e])
                      + (m * (double)Wgg[g] + c * (double)Wgg[NG + g] + (double)bgg[g]);
            l[e] = v2; mx = fmax(mx, v2);
        }
        double sf[NE], Z = 0.0;
        #pragma unroll
        for (int e = 0; e < NE; e++) { sf[e] = exp(l[e] - mx); Z += sf[e]; }
        int e0 = 0;
        #pragma unroll
        for (int e = 1; e < NE; e++) if (sf[e] > sf[e0]) e0 = e;
        int e1 = (e0 == 0) ? 1 : 0;
        #pragma unroll
        for (int e = 0; e < NE; e++) if (e != e0 && sf[e] > sf[e1]) e1 = e;
        double s0 = sf[e0] / Z, s1 = sf[e1] / Z;
        double den = s0 + s1 + 1e-9;

        g_routeE[2 * b] = e0; g_routeE[2 * b + 1] = e1;
        g_routeW[2 * b] = (float)(s0 / den); g_routeW[2 * b + 1] = (float)(s1 / den);
        atomicAdd(&g_count[e0], 1);
        atomicAdd(&g_count[e1], 1);
    }
}

// ---------------- scatter (256-aligned segments; prefix computed locally) ----------------
__global__ __launch_bounds__(128) void scatter_kernel() {
    int b = blockIdx.x * 128 + threadIdx.x;
    int off[NE + 1];
    off[0] = 0;
    #pragma unroll
    for (int e = 0; e < NE; e++)
        off[e + 1] = off[e] + ((g_count[e] + 255) & ~255);
    if (b == 0) {
        #pragma unroll
        for (int e = 0; e <= NE; e++) g_padOff[e] = off[e];
        g_Mtot = off[NE];
    }
    if (b >= BATCH) return;
    #pragma unroll
    for (int j = 0; j < 2; j++) {
        int e = g_routeE[2 * b + j];
        int pos = off[e] + atomicAdd(&g_cursor[e], 1);
        g_assignRow[pos] = b;
        g_assignW[pos]   = g_routeW[2 * b + j];
    }
}

// ---------------- helpers ----------------
__device__ __forceinline__ uint2 pack4h(float4 v) {
    __half2 h01 = __floats2half2_rn(v.x, v.y);
    __half2 h23 = __floats2half2_rn(v.z, v.w);
    uint2 r;
    r.x = *(uint32_t*)&h01;
    r.y = *(uint32_t*)&h23;
    return r;
}

// =====================================================================
// fp16 single-pass WMMA GEMM: CTA tile 256x64, 8 warps (4m x 2n) of
// warp tile 64x32 (4x2 wmma 16x16x16), KCH=16, 2-stage double buffer
// + 1-deep register prefetch, fp32 accumulate.
// =====================================================================

// ---------------- GEMM1: H = fp16(relu(X[rows] @ W1[e] + b1[e])); W1 is [k][n] ----------------
__global__ __launch_bounds__(256, 2) void wmma_gemm1(
    const float* __restrict__ x, const float* __restrict__ W1, const float* __restrict__ b1)
{
    __shared__ __align__(16) char smem[SMEM_BYTES];
    __shared__ int s_row[256];

    int m0 = blockIdx.y * 256;
    if (m0 >= g_Mtot) return;
    int e = 0;
    #pragma unroll
    for (int i = 1; i < NE; i++) if (m0 >= g_padOff[i]) e = i;
    int n0 = blockIdx.x * 64;
    int tid = threadIdx.x, wid = tid >> 5;
    int wm = wid & 3, wn = wid >> 2;

    {   // gather row indices (256 rows)
        int r0 = g_assignRow[m0 + tid];
        s_row[tid] = r0 < 0 ? 0 : r0;
    }
    __syncthreads();

    const float* Wb = W1 + (size_t)e * DIM * PP;

    // staging: A 256x16 fp32 = 1024 float4 (4/thread); B 16x64 fp32 = 256 float4 (1/thread)
    int arow = tid >> 2, aq = tid & 3;
    int brow = tid >> 4, bq = tid & 15;
    const float* aP[4];
    #pragma unroll
    for (int j = 0; j < 4; j++)
        aP[j] = x + (size_t)s_row[arow + 64 * j] * DIM + aq * 4;
    const float* bP = Wb + (size_t)brow * PP + n0 + bq * 4;

    float4 ra[4], rb;
    #pragma unroll
    for (int j = 0; j < 4; j++) ra[j] = *(const float4*)aP[j];
    rb = *(const float4*)bP;

    wmma::fragment<wmma::accumulator, 16, 16, 16, float> acc[4][2];
    #pragma unroll
    for (int mi = 0; mi < 4; mi++)
        #pragma unroll
        for (int ni = 0; ni < 2; ni++)
            wmma::fill_fragment(acc[mi][ni], 0.0f);

    const int NK = DIM / KCH;   // 128
    for (int k = 0; k < NK; k++) {
        int s = k & 1;
        __half* sA = (__half*)(smem + SA(s));
        __half* sB = (__half*)(smem + SB(s));

        #pragma unroll
        for (int j = 0; j < 4; j++)
            *(uint2*)&sA[(arow + 64 * j) * 24 + aq * 4] = pack4h(ra[j]);
        *(uint2*)&sB[brow * 72 + bq * 4] = pack4h(rb);
        __syncthreads();

        if (k + 1 < NK) {       // prefetch next chunk (1-deep)
            int k0 = (k + 1) * KCH;
            #pragma unroll
            for (int j = 0; j < 4; j++) ra[j] = *(const float4*)(aP[j] + k0);
            rb = *(const float4*)(bP + (size_t)k0 * PP);
        }

        wmma::fragment<wmma::matrix_a, 16, 16, 16, __half, wmma::row_major> af[4];
        wmma::fragment<wmma::matrix_b, 16, 16, 16, __half, wmma::row_major> bf[2];
        #pragma unroll
        for (int mi = 0; mi < 4; mi++)
            wmma::load_matrix_sync(af[mi], &sA[(wm * 64 + mi * 16) * 24], 24);
        #pragma unroll
        for (int ni = 0; ni < 2; ni++)
            wmma::load_matrix_sync(bf[ni], &sB[wn * 32 + ni * 16], 72);
        #pragma unroll
        for (int mi = 0; mi < 4; mi++)
            #pragma unroll
            for (int ni = 0; ni < 2; ni++)
                wmma::mma_sync(acc[mi][ni], af[mi], bf[ni], acc[mi][ni]);
    }
    __syncthreads();

    // epilogue in two 128-row halves through the fp32 Cbuf
    float* Cbuf = (float*)smem;
    const float* bb = b1 + e * PP;
    #pragma unroll
    for (int h = 0; h < 2; h++) {
        if ((wm >> 1) == h) {
            #pragma unroll
            for (int mi = 0; mi < 4; mi++)
                #pragma unroll
                for (int ni = 0; ni < 2; ni++)
                    wmma::store_matrix_sync(
                        &Cbuf[((wm & 1) * 64 + mi * 16) * CBUF_LD + wn * 32 + ni * 16],
                        acc[mi][ni], CBUF_LD, wmma::mem_row_major);
        }
        __syncthreads();
        #pragma unroll
        for (int j = 0; j < 16; j++) {
            int idx = tid + 256 * j;               // 128 rows x 32 col-pairs
            int r = idx >> 5, c = (idx & 31) * 2;
            int col = n0 + c;
            float v0 = fmaxf(Cbuf[r * CBUF_LD + c]     + bb[col],     0.f);
            float v1 = fmaxf(Cbuf[r * CBUF_LD + c + 1] + bb[col + 1], 0.f);
            __half2 hv = __floats2half2_rn(v0, v1);
            *(__half2*)&g_Hh[(size_t)(m0 + h * 128 + r) * PP + col] = hv;
        }
        __syncthreads();
    }
}

// ---------------- GEMM2: out[row] += w * (H @ W2[e] + b2[e]); W2 is [k][n] ----------------
__global__ __launch_bounds__(256, 2) void wmma_gemm2(
    const float* __restrict__ W2, const float* __restrict__ b2, float* __restrict__ out)
{
    __shared__ __align__(16) char smem[SMEM_BYTES];
    __shared__ int   s_rowR[256];
    __shared__ float s_w[256];

    int m0 = blockIdx.y * 256;
    if (m0 >= g_Mtot) return;
    int e = 0;
    #pragma unroll
    for (int i = 1; i < NE; i++) if (m0 >= g_padOff[i]) e = i;
    int n0 = blockIdx.x * 64;
    int tid = threadIdx.x, wid = tid >> 5;
    int wm = wid & 3, wn = wid >> 2;

    s_rowR[tid] = g_assignRow[m0 + tid];
    s_w[tid]    = g_assignW[m0 + tid];
    __syncthreads();

    const float* Wb = W2 + (size_t)e * PP * DIM;

    // staging: A 256x16 fp16 = 512 uint4 (2/thread); B 16x64 fp32 = 256 float4 (1/thread)
    int arow = tid >> 1, aq = tid & 1;
    int brow = tid >> 4, bq = tid & 15;
    const __half* aP0 = g_Hh + (size_t)(m0 + arow) * PP + aq * 8;
    const __half* aP1 = g_Hh + (size_t)(m0 + arow + 128) * PP + aq * 8;
    const float* bP = Wb + (size_t)brow * DIM + n0 + bq * 4;

    uint4 ra0 = *(const uint4*)aP0;
    uint4 ra1 = *(const uint4*)aP1;
    float4 rb = *(const float4*)bP;

    wmma::fragment<wmma::accumulator, 16, 16, 16, float> acc[4][2];
    #pragma unroll
    for (int mi = 0; mi < 4; mi++)
        #pragma unroll
        for (int ni = 0; ni < 2; ni++)
            wmma::fill_fragment(acc[mi][ni], 0.0f);

    const int NK = PP / KCH;    // 32
    for (int k = 0; k < NK; k++) {
        int s = k & 1;
        __half* sA = (__half*)(smem + SA(s));
        __half* sB = (__half*)(smem + SB(s));

        *(uint4*)&sA[arow * 24 + aq * 8] = ra0;
        *(uint4*)&sA[(arow + 128) * 24 + aq * 8] = ra1;
        *(uint2*)&sB[brow * 72 + bq * 4] = pack4h(rb);
        __syncthreads();

        if (k + 1 < NK) {
            int k0 = (k + 1) * KCH;
            ra0 = *(const uint4*)(aP0 + k0);
            ra1 = *(const uint4*)(aP1 + k0);
            rb  = *(const float4*)(bP + (size_t)k0 * DIM);
        }

        wmma::fragment<wmma::matrix_a, 16, 16, 16, __half, wmma::row_major> af[4];
        wmma::fragment<wmma::matrix_b, 16, 16, 16, __half, wmma::row_major> bf[2];
        #pragma unroll
        for (int mi = 0; mi < 4; mi++)
            wmma::load_matrix_sync(af[mi], &sA[(wm * 64 + mi * 16) * 24], 24);
        #pragma unroll
        for (int ni = 0; ni < 2; ni++)
            wmma::load_matrix_sync(bf[ni], &sB[wn * 32 + ni * 16], 72);
        #pragma unroll
        for (int mi = 0; mi < 4; mi++)
            #pragma unroll
            for (int ni = 0; ni < 2; ni++)
                wmma::mma_sync(acc[mi][ni], af[mi], bf[ni], acc[mi][ni]);
    }
    __syncthreads();

    // epilogue halves: Cbuf -> gated atomicAdd into out (2 commutative adds/element)
    float* Cbuf = (float*)smem;
    const float* bb = b2 + e * DIM;
    #pragma unroll
    for (int h = 0; h < 2; h++) {
        if ((wm >> 1) == h) {
            #pragma unroll
            for (int mi = 0; mi < 4; mi++)
                #pragma unroll
                for (int ni = 0; ni < 2; ni++)
                    wmma::store_matrix_sync(
                        &Cbuf[((wm & 1) * 64 + mi * 16) * CBUF_LD + wn * 32 + ni * 16],
                        acc[mi][ni], CBUF_LD, wmma::mem_row_major);
        }
        __syncthreads();
        #pragma unroll
        for (int j = 0; j < 16; j++) {
            int idx = tid + 256 * j;               // 128 rows x 32 col-pairs
            int r = idx >> 5, c = (idx & 31) * 2;
            int ar = h * 128 + r;
            int row = s_rowR[ar];
            if (row >= 0) {
                float w = s_w[ar];
                int col = n0 + c;
                float* orow = out + (size_t)row * DIM;
                atomicAdd(&orow[col],     w * (Cbuf[r * CBUF_LD + c]     + bb[col]));
                atomicAdd(&orow[col + 1], w * (Cbuf[r * CBUF_LD + c + 1] + bb[col + 1]));
            }
        }
        __syncthreads();
    }
}

// ---------------- launch ----------------
extern "C" void kernel_launch(void* const* d_in, const int* in_sizes, int n_in,
                              void* d_out, int out_size)
{
    const float* x   = (const float*)d_in[0];
    const float* Wg  = (const float*)d_in[1];
    const float* bg  = (const float*)d_in[2];
    const float* Wp  = (const float*)d_in[3];
    const float* bp  = (const float*)d_in[4];
    const float* Wgg = (const float*)d_in[5];
    const float* bgg = (const float*)d_in[6];
    const float* W1  = (const float*)d_in[7];
    const float* b1  = (const float*)d_in[8];
    const float* W2  = (const float*)d_in[9];
    const float* b2  = (const float*)d_in[10];
    float* out = (float*)d_out;

    init_kernel<<<16384, 256>>>((float4*)out);                   // launch 0
    route_kernel<<<BATCH, 1024>>>(x, Wg, bg, Wp, bp, Wgg, bgg);  // launch 1
    scatter_kernel<<<(BATCH + 127) / 128, 128>>>();              // launch 2
    wmma_gemm1<<<dim3(PP / 64, MT), 256>>>(x, W1, b1);           // launch 3 <- profiled slot
    wmma_gemm2<<<dim3(DIM / 64, MT), 256>>>(W2, b2, out);        // launch 4
}

// round 13
// speedup vs baseline: 1.8382x; 1.0777x over previous
#include <cuda_runtime.h>
#include <cuda_bf16.h>
#include <cuda_fp16.h>
#include <mma.h>
#include <math.h>
#include <stdint.h>

using namespace nvcuda;

// ---------------- problem constants ----------------
#define BATCH 8192
#define DIM   2048
#define NE    8
#define NG    4
#define PP    512
#define HH    192
#define CAP   18432          // 2*BATCH + 8*255 rounded up to 256-row tiles
#define MT    72             // CAP/256
#define KCH   16             // K elems per smem chunk (2-stage double buffer)

// ---------------- device scratch (~19 MB — proven-safe envelope) ----------------
__device__ int   g_count[NE];
__device__ int   g_cursor[NE];
__device__ int   g_padOff[NE + 1];
__device__ int   g_Mtot;
__device__ int   g_routeE[2 * BATCH];
__device__ float g_routeW[2 * BATCH];
__device__ __align__(1024) int   g_assignRow[CAP];
__device__ __align__(1024) float g_assignW[CAP];
__device__ __align__(1024) __half g_Hh[(size_t)CAP * PP];

// ---------------- smem layout ----------------
#define SA(s)  ((s) * 12288)
#define SB(s)  (24576 + (s) * 2304)
#define CBUF_LD 68
#define SMEM_BYTES 34816

// ---------------- init: zero output + scratch ----------------
__global__ __launch_bounds__(256) void init_kernel(float4* __restrict__ out4) {
    int i = blockIdx.x * 256 + threadIdx.x;           // 16384 x 256 = BATCH*DIM/4
    if (i < (BATCH * DIM) / 4) out4[i] = make_float4(0.f, 0.f, 0.f, 0.f);
    if (i < CAP) { g_assignRow[i] = -1; g_assignW[i] = 0.f; }
    if (i < NE)  { g_count[i] = 0; g_cursor[i] = 0; }
}

// ---------------- fast fp32-accurate cos(a)+sin(a) ----------------
// double Cody-Waite range reduction (k <= ~90 here), fp32 minimax polys.
// abs error ~1e-7 — same class as XLA's fp32 trig; routing margin ~1e-3.
__device__ __forceinline__ float cos_plus_sin(float ang) {
    double da = (double)ang;
    double kd = rint(da * 0.63661977236758138);        // 2/pi
    int q = ((int)kd) & 3;                             // two's-complement mod 4
    float r = (float)(da - kd * 1.5707963267948966);   // r in [-pi/4, pi/4]
    float r2 = r * r;
    float s = r + r * r2 * (-1.6666654611e-1f
              + r2 * (8.3321608736e-3f + r2 * (-1.9515295891e-4f)));
    float c = 1.0f + r2 * (-0.5f + r2 * (4.166664568298827e-2f
              + r2 * (-1.388731625493765e-3f + r2 * 2.443315711809948e-5f)));
    float cs = c + s, cm = c - s;
    float v = (q & 1) ? cm : cs;
    return (q & 2) ? -v : v;
}

// ---------------- routing (qm reduction tree bit-identical to passing rounds) ----------------
__global__ __launch_bounds__(1024) void route_kernel(
    const float* __restrict__ x,
    const float* __restrict__ Wg, const float* __restrict__ bg,
    const float* __restrict__ Wp, const float* __restrict__ bp,
    const float* __restrict__ Wgg, const float* __restrict__ bgg)
{
    __shared__ float  warpSum[32];
    __shared__ double dWarp[32];
    __shared__ float  sh_qm;
    int b = blockIdx.x, tid = threadIdx.x;

    const float2* xr = (const float2*)(x + (size_t)b * DIM);
    float2 v = xr[tid];
    float acc = v.x + v.y;
    #pragma unroll
    for (int o = 16; o; o >>= 1) acc += __shfl_down_sync(0xffffffffu, acc, o);
    if ((tid & 31) == 0) warpSum[tid >> 5] = acc;
    __syncthreads();
    if (tid < 32) {
        float a2 = warpSum[tid];
        #pragma unroll
        for (int o = 16; o; o >>= 1) a2 += __shfl_down_sync(0xffffffffu, a2, o);
        if (tid == 0) sh_qm = a2 * (1.0f / 2048.0f);
    }
    __syncthreads();
    float qm = sh_qm;

    double tr = 0.0;
    if (tid < HH) {
        float ang = __fmul_rn(qm, (float)(7 * (tid + 1)));
        tr = (double)cos_plus_sin(ang);
    }
    #pragma unroll
    for (int o = 16; o; o >>= 1) tr += __shfl_down_sync(0xffffffffu, tr, o);
    if ((tid & 31) == 0) dWarp[tid >> 5] = tr;
    __syncthreads();

    if (tid == 0) {
        double t = 0.0;
        #pragma unroll
        for (int i = 0; i < 32; i++) t += dWarp[i];
        double m = t / 384.0;
        const double c = 0.015625;   // KTOP/D: LIF spike rate is exactly constant

        double l[NE]; double mx = -1e300;
        #pragma unroll
        for (int e = 0; e < NE; e++) {
            int g = e & (NG - 1);
            double v2 = (m * (double)Wg[e] + c * (double)Wg[NE + e] + (double)bg[e])
                      - 0.1 * (m * (double)Wp[e] + c * (double)Wp[NE + e] + (double)bp[e])
                      + (m * (double)Wgg[g] + c * (double)Wgg[NG + g] + (double)bgg[g]);
            l[e] = v2; mx = fmax(mx, v2);
        }
        double sf[NE], Z = 0.0;
        #pragma unroll
        for (int e = 0; e < NE; e++) { sf[e] = exp(l[e] - mx); Z += sf[e]; }
        int e0 = 0;
        #pragma unroll
        for (int e = 1; e < NE; e++) if (sf[e] > sf[e0]) e0 = e;
        int e1 = (e0 == 0) ? 1 : 0;
        #pragma unroll
        for (int e = 0; e < NE; e++) if (e != e0 && sf[e] > sf[e1]) e1 = e;
        double s0 = sf[e0] / Z, s1 = sf[e1] / Z;
        double den = s0 + s1 + 1e-9;

        g_routeE[2 * b] = e0; g_routeE[2 * b + 1] = e1;
        g_routeW[2 * b] = (float)(s0 / den); g_routeW[2 * b + 1] = (float)(s1 / den);
        atomicAdd(&g_count[e0], 1);
        atomicAdd(&g_count[e1], 1);
    }
}

// ---------------- scatter (256-aligned segments; prefix computed locally) ----------------
__global__ __launch_bounds__(128) void scatter_kernel() {
    int b = blockIdx.x * 128 + threadIdx.x;
    int off[NE + 1];
    off[0] = 0;
    #pragma unroll
    for (int e = 0; e < NE; e++)
        off[e + 1] = off[e] + ((g_count[e] + 255) & ~255);
    if (b == 0) {
        #pragma unroll
        for (int e = 0; e <= NE; e++) g_padOff[e] = off[e];
        g_Mtot = off[NE];
    }
    if (b >= BATCH) return;
    #pragma unroll
    for (int j = 0; j < 2; j++) {
        int e = g_routeE[2 * b + j];
        int pos = off[e] + atomicAdd(&g_cursor[e], 1);
        g_assignRow[pos] = b;
        g_assignW[pos]   = g_routeW[2 * b + j];
    }
}

// ---------------- helpers ----------------
__device__ __forceinline__ uint2 pack4h(float4 v) {
    __half2 h01 = __floats2half2_rn(v.x, v.y);
    __half2 h23 = __floats2half2_rn(v.z, v.w);
    uint2 r;
    r.x = *(uint32_t*)&h01;
    r.y = *(uint32_t*)&h23;
    return r;
}

// =====================================================================
// fp16 single-pass WMMA GEMM: CTA tile 256x64, 8 warps (4m x 2n) of
// warp tile 64x32 (4x2 wmma 16x16x16), KCH=16, 2-stage double buffer
// + 1-deep register prefetch, fp32 accumulate.  (identical to R11)
// =====================================================================

// ---------------- GEMM1: H = fp16(relu(X[rows] @ W1[e] + b1[e])); W1 is [k][n] ----------------
__global__ __launch_bounds__(256, 2) void wmma_gemm1(
    const float* __restrict__ x, const float* __restrict__ W1, const float* __restrict__ b1)
{
    __shared__ __align__(16) char smem[SMEM_BYTES];
    __shared__ int s_row[256];

    int m0 = blockIdx.y * 256;
    if (m0 >= g_Mtot) return;
    int e = 0;
    #pragma unroll
    for (int i = 1; i < NE; i++) if (m0 >= g_padOff[i]) e = i;
    int n0 = blockIdx.x * 64;
    int tid = threadIdx.x, wid = tid >> 5;
    int wm = wid & 3, wn = wid >> 2;

    {
        int r0 = g_assignRow[m0 + tid];
        s_row[tid] = r0 < 0 ? 0 : r0;
    }
    __syncthreads();

    const float* Wb = W1 + (size_t)e * DIM * PP;

    int arow = tid >> 2, aq = tid & 3;
    int brow = tid >> 4, bq = tid & 15;
    const float* aP[4];
    #pragma unroll
    for (int j = 0; j < 4; j++)
        aP[j] = x + (size_t)s_row[arow + 64 * j] * DIM + aq * 4;
    const float* bP = Wb + (size_t)brow * PP + n0 + bq * 4;

    float4 ra[4], rb;
    #pragma unroll
    for (int j = 0; j < 4; j++) ra[j] = *(const float4*)aP[j];
    rb = *(const float4*)bP;

    wmma::fragment<wmma::accumulator, 16, 16, 16, float> acc[4][2];
    #pragma unroll
    for (int mi = 0; mi < 4; mi++)
        #pragma unroll
        for (int ni = 0; ni < 2; ni++)
            wmma::fill_fragment(acc[mi][ni], 0.0f);

    const int NK = DIM / KCH;   // 128
    for (int k = 0; k < NK; k++) {
        int s = k & 1;
        __half* sA = (__half*)(smem + SA(s));
        __half* sB = (__half*)(smem + SB(s));

        #pragma unroll
        for (int j = 0; j < 4; j++)
            *(uint2*)&sA[(arow + 64 * j) * 24 + aq * 4] = pack4h(ra[j]);
        *(uint2*)&sB[brow * 72 + bq * 4] = pack4h(rb);
        __syncthreads();

        if (k + 1 < NK) {
            int k0 = (k + 1) * KCH;
            #pragma unroll
            for (int j = 0; j < 4; j++) ra[j] = *(const float4*)(aP[j] + k0);
            rb = *(const float4*)(bP + (size_t)k0 * PP);
        }

        wmma::fragment<wmma::matrix_a, 16, 16, 16, __half, wmma::row_major> af[4];
        wmma::fragment<wmma::matrix_b, 16, 16, 16, __half, wmma::row_major> bf[2];
        #pragma unroll
        for (int mi = 0; mi < 4; mi++)
            wmma::load_matrix_sync(af[mi], &sA[(wm * 64 + mi * 16) * 24], 24);
        #pragma unroll
        for (int ni = 0; ni < 2; ni++)
            wmma::load_matrix_sync(bf[ni], &sB[wn * 32 + ni * 16], 72);
        #pragma unroll
        for (int mi = 0; mi < 4; mi++)
            #pragma unroll
            for (int ni = 0; ni < 2; ni++)
                wmma::mma_sync(acc[mi][ni], af[mi], bf[ni], acc[mi][ni]);
    }
    __syncthreads();

    float* Cbuf = (float*)smem;
    const float* bb = b1 + e * PP;
    #pragma unroll
    for (int h = 0; h < 2; h++) {
        if ((wm >> 1) == h) {
            #pragma unroll
            for (int mi = 0; mi < 4; mi++)
                #pragma unroll
                for (int ni = 0; ni < 2; ni++)
                    wmma::store_matrix_sync(
                        &Cbuf[((wm & 1) * 64 + mi * 16) * CBUF_LD + wn * 32 + ni * 16],
                        acc[mi][ni], CBUF_LD, wmma::mem_row_major);
        }
        __syncthreads();
        #pragma unroll
        for (int j = 0; j < 16; j++) {
            int idx = tid + 256 * j;
            int r = idx >> 5, c = (idx & 31) * 2;
            int col = n0 + c;
            float v0 = fmaxf(Cbuf[r * CBUF_LD + c]     + bb[col],     0.f);
            float v1 = fmaxf(Cbuf[r * CBUF_LD + c + 1] + bb[col + 1], 0.f);
            __half2 hv = __floats2half2_rn(v0, v1);
            *(__half2*)&g_Hh[(size_t)(m0 + h * 128 + r) * PP + col] = hv;
        }
        __syncthreads();
    }
}

// ---------------- GEMM2: out[row] += w * (H @ W2[e] + b2[e]); W2 is [k][n] ----------------
__global__ __launch_bounds__(256, 2) void wmma_gemm2(
    const float* __restrict__ W2, const float* __restrict__ b2, float* __restrict__ out)
{
    __shared__ __align__(16) char smem[SMEM_BYTES];
    __shared__ int   s_rowR[256];
    __shared__ float s_w[256];

    int m0 = blockIdx.y * 256;
    if (m0 >= g_Mtot) return;
    int e = 0;
    #pragma unroll
    for (int i = 1; i < NE; i++) if (m0 >= g_padOff[i]) e = i;
    int n0 = blockIdx.x * 64;
    int tid = threadIdx.x, wid = tid >> 5;
    int wm = wid & 3, wn = wid >> 2;

    s_rowR[tid] = g_assignRow[m0 + tid];
    s_w[tid]    = g_assignW[m0 + tid];
    __syncthreads();

    const float* Wb = W2 + (size_t)e * PP * DIM;

    int arow = tid >> 1, aq = tid & 1;
    int brow = tid >> 4, bq = tid & 15;
    const __half* aP0 = g_Hh + (size_t)(m0 + arow) * PP + aq * 8;
    const __half* aP1 = g_Hh + (size_t)(m0 + arow + 128) * PP + aq * 8;
    const float* bP = Wb + (size_t)brow * DIM + n0 + bq * 4;

    uint4 ra0 = *(const uint4*)aP0;
    uint4 ra1 = *(const uint4*)aP1;
    float4 rb = *(const float4*)bP;

    wmma::fragment<wmma::accumulator, 16, 16, 16, float> acc[4][2];
    #pragma unroll
    for (int mi = 0; mi < 4; mi++)
        #pragma unroll
        for (int ni = 0; ni < 2; ni++)
            wmma::fill_fragment(acc[mi][ni], 0.0f);

    const int NK = PP / KCH;    // 32
    for (int k = 0; k < NK; k++) {
        int s = k & 1;
        __half* sA = (__half*)(smem + SA(s));
        __half* sB = (__half*)(smem + SB(s));

        *(uint4*)&sA[arow * 24 + aq * 8] = ra0;
        *(uint4*)&sA[(arow + 128) * 24 + aq * 8] = ra1;
        *(uint2*)&sB[brow * 72 + bq * 4] = pack4h(rb);
        __syncthreads();

        if (k + 1 < NK) {
            int k0 = (k + 1) * KCH;
            ra0 = *(const uint4*)(aP0 + k0);
            ra1 = *(const uint4*)(aP1 + k0);
            rb  = *(const float4*)(bP + (size_t)k0 * DIM);
        }

        wmma::fragment<wmma::matrix_a, 16, 16, 16, __half, wmma::row_major> af[4];
        wmma::fragment<wmma::matrix_b, 16, 16, 16, __half, wmma::row_major> bf[2];
        #pragma unroll
        for (int mi = 0; mi < 4; mi++)
            wmma::load_matrix_sync(af[mi], &sA[(wm * 64 + mi * 16) * 24], 24);
        #pragma unroll
        for (int ni = 0; ni < 2; ni++)
            wmma::load_matrix_sync(bf[ni], &sB[wn * 32 + ni * 16], 72);
        #pragma unroll
        for (int mi = 0; mi < 4; mi++)
            #pragma unroll
            for (int ni = 0; ni < 2; ni++)
                wmma::mma_sync(acc[mi][ni], af[mi], bf[ni], acc[mi][ni]);
    }
    __syncthreads();

    float* Cbuf = (float*)smem;
    const float* bb = b2 + e * DIM;
    #pragma unroll
    for (int h = 0; h < 2; h++) {
        if ((wm >> 1) == h) {
            #pragma unroll
            for (int mi = 0; mi < 4; mi++)
                #pragma unroll
                for (int ni = 0; ni < 2; ni++)
                    wmma::store_matrix_sync(
                        &Cbuf[((wm & 1) * 64 + mi * 16) * CBUF_LD + wn * 32 + ni * 16],
                        acc[mi][ni], CBUF_LD, wmma::mem_row_major);
        }
        __syncthreads();
        #pragma unroll
        for (int j = 0; j < 16; j++) {
            int idx = tid + 256 * j;
            int r = idx >> 5, c = (idx & 31) * 2;
            int ar = h * 128 + r;
            int row = s_rowR[ar];
            if (row >= 0) {
                float w = s_w[ar];
                int col = n0 + c;
                float* orow = out + (size_t)row * DIM;
                atomicAdd(&orow[col],     w * (Cbuf[r * CBUF_LD + c]     + bb[col]));
                atomicAdd(&orow[col + 1], w * (Cbuf[r * CBUF_LD + c + 1] + bb[col + 1]));
            }
        }
        __syncthreads();
    }
}

// ---------------- launch ----------------
extern "C" void kernel_launch(void* const* d_in, const int* in_sizes, int n_in,
                              void* d_out, int out_size)
{
    const float* x   = (const float*)d_in[0];
    const float* Wg  = (const float*)d_in[1];
    const float* bg  = (const float*)d_in[2];
    const float* Wp  = (const float*)d_in[3];
    const float* bp  = (const float*)d_in[4];
    const float* Wgg = (const float*)d_in[5];
    const float* bgg = (const float*)d_in[6];
    const float* W1  = (const float*)d_in[7];
    const float* b1  = (const float*)d_in[8];
    const float* W2  = (const float*)d_in[9];
    const float* b2  = (const float*)d_in[10];
    float* out = (float*)d_out;

    init_kernel<<<16384, 256>>>((float4*)out);                   // launch 0
    route_kernel<<<BATCH, 1024>>>(x, Wg, bg, Wp, bp, Wgg, bgg);  // launch 1
    scatter_kernel<<<(BATCH + 127) / 128, 128>>>();              // launch 2
    wmma_gemm1<<<dim3(PP / 64, MT), 256>>>(x, W1, b1);           // launch 3 <- profiled slot
    wmma_gemm2<<<dim3(DIM / 64, MT), 256>>>(W2, b2, out);        // launch 4
}

// round 14
// speedup vs baseline: 3.1882x; 1.7344x over previous
#include <cuda_runtime.h>
#include <cuda_bf16.h>
#include <cuda_fp16.h>
#include <mma.h>
#include <math.h>
#include <stdint.h>

using namespace nvcuda;

// ---------------- problem constants ----------------
#define BATCH 8192
#define DIM   2048
#define NE    8
#define NG    4
#define PP    512
#define HH    192
#define CAP   18432          // 2*BATCH + 8*255 rounded up to 256-row tiles
#define MT    72             // CAP/256
#define KCH   16             // K elems per smem chunk (2-stage double buffer)

// ---------------- device scratch (~95 MB total — envelope probe) ----------------
__device__ int   g_count[NE];
__device__ int   g_cursor[NE];
__device__ int   g_padOff[NE + 1];
__device__ int   g_Mtot;
__device__ int   g_routeE[2 * BATCH];
__device__ float g_routeW[2 * BATCH];
__device__ int   g_pos[2 * BATCH];
__device__ __align__(1024) int   g_assignRow[CAP];
__device__ __align__(1024) float g_assignW[CAP];
__device__ __align__(1024) __half g_Hh[(size_t)CAP * PP];
__device__ __align__(1024) __half g_Yh[(size_t)CAP * DIM];

// ---------------- smem layout ----------------
#define SA(s)  ((s) * 12288)
#define SB(s)  (24576 + (s) * 2304)
#define CBUF_LD 68
#define SMEM_BYTES 34816

// ---------------- init: scratch only (out no longer needs zeroing) ----------------
__global__ __launch_bounds__(256) void init_kernel() {
    int i = blockIdx.x * 256 + threadIdx.x;
    if (i < CAP) { g_assignRow[i] = -1; g_assignW[i] = 0.f; }
    if (i < NE)  { g_count[i] = 0; g_cursor[i] = 0; }
}

// ---------------- fast fp32-accurate cos(a)+sin(a) ----------------
__device__ __forceinline__ float cos_plus_sin(float ang) {
    double da = (double)ang;
    double kd = rint(da * 0.63661977236758138);        // 2/pi
    int q = ((int)kd) & 3;
    float r = (float)(da - kd * 1.5707963267948966);   // r in [-pi/4, pi/4]
    float r2 = r * r;
    float s = r + r * r2 * (-1.6666654611e-1f
              + r2 * (8.3321608736e-3f + r2 * (-1.9515295891e-4f)));
    float c = 1.0f + r2 * (-0.5f + r2 * (4.166664568298827e-2f
              + r2 * (-1.388731625493765e-3f + r2 * 2.443315711809948e-5f)));
    float cs = c + s, cm = c - s;
    float v = (q & 1) ? cm : cs;
    return (q & 2) ? -v : v;
}

// ---------------- routing (qm tree + selection path bit-identical; weights fp32) ----------------
__global__ __launch_bounds__(1024) void route_kernel(
    const float* __restrict__ x,
    const float* __restrict__ Wg, const float* __restrict__ bg,
    const float* __restrict__ Wp, const float* __restrict__ bp,
    const float* __restrict__ Wgg, const float* __restrict__ bgg)
{
    __shared__ float  warpSum[32];
    __shared__ double dWarp[32];
    __shared__ float  sh_qm;
    int b = blockIdx.x, tid = threadIdx.x;

    const float2* xr = (const float2*)(x + (size_t)b * DIM);
    float2 v = xr[tid];
    float acc = v.x + v.y;
    #pragma unroll
    for (int o = 16; o; o >>= 1) acc += __shfl_down_sync(0xffffffffu, acc, o);
    if ((tid & 31) == 0) warpSum[tid >> 5] = acc;
    __syncthreads();
    if (tid < 32) {
        float a2 = warpSum[tid];
        #pragma unroll
        for (int o = 16; o; o >>= 1) a2 += __shfl_down_sync(0xffffffffu, a2, o);
        if (tid == 0) sh_qm = a2 * (1.0f / 2048.0f);
    }
    __syncthreads();
    float qm = sh_qm;

    double tr = 0.0;
    if (tid < HH) {
        float ang = __fmul_rn(qm, (float)(7 * (tid + 1)));
        tr = (double)cos_plus_sin(ang);
    }
    #pragma unroll
    for (int o = 16; o; o >>= 1) tr += __shfl_down_sync(0xffffffffu, tr, o);
    if ((tid & 31) == 0) dWarp[tid >> 5] = tr;
    __syncthreads();

    if (tid == 0) {
        double t = 0.0;
        #pragma unroll
        for (int i = 0; i < 32; i++) t += dWarp[i];
        double m = t / 384.0;
        const double c = 0.015625;   // KTOP/D: LIF spike rate is exactly constant

        double l[NE]; double mx = -1e300;
        #pragma unroll
        for (int e = 0; e < NE; e++) {
            int g = e & (NG - 1);
            double v2 = (m * (double)Wg[e] + c * (double)Wg[NE + e] + (double)bg[e])
                      - 0.1 * (m * (double)Wp[e] + c * (double)Wp[NE + e] + (double)bp[e])
                      + (m * (double)Wgg[g] + c * (double)Wgg[NG + g] + (double)bgg[g]);
            l[e] = v2; mx = fmax(mx, v2);
        }
        // top-2 selection via double logit compare (exp is monotone: identical result,
        // identical tie behavior to comparing softmax values)
        int e0 = 0;
        #pragma unroll
        for (int e = 1; e < NE; e++) if (l[e] > l[e0]) e0 = e;
        int e1 = (e0 == 0) ? 1 : 0;
        #pragma unroll
        for (int e = 0; e < NE; e++) if (e != e0 && l[e] > l[e1]) e1 = e;
        // weights (continuous in inputs — fp32 precision is ample; matches JAX fp32 softmax)
        float mxf = (float)mx;
        float sf[NE], Zf = 0.f;
        #pragma unroll
        for (int e = 0; e < NE; e++) { sf[e] = __expf((float)l[e] - mxf); Zf += sf[e]; }
        float s0 = sf[e0] / Zf, s1 = sf[e1] / Zf;
        float den = s0 + s1 + 1e-9f;

        g_routeE[2 * b] = e0; g_routeE[2 * b + 1] = e1;
        g_routeW[2 * b] = s0 / den; g_routeW[2 * b + 1] = s1 / den;
        atomicAdd(&g_count[e0], 1);
        atomicAdd(&g_count[e1], 1);
    }
}

// ---------------- scatter (256-aligned segments; prefix computed locally) ----------------
__global__ __launch_bounds__(128) void scatter_kernel() {
    int b = blockIdx.x * 128 + threadIdx.x;
    int off[NE + 1];
    off[0] = 0;
    #pragma unroll
    for (int e = 0; e < NE; e++)
        off[e + 1] = off[e] + ((g_count[e] + 255) & ~255);
    if (b == 0) {
        #pragma unroll
        for (int e = 0; e <= NE; e++) g_padOff[e] = off[e];
        g_Mtot = off[NE];
    }
    if (b >= BATCH) return;
    #pragma unroll
    for (int j = 0; j < 2; j++) {
        int e = g_routeE[2 * b + j];
        int pos = off[e] + atomicAdd(&g_cursor[e], 1);
        g_assignRow[pos] = b;
        g_assignW[pos]   = g_routeW[2 * b + j];
        g_pos[2 * b + j] = pos;
    }
}

// ---------------- helpers ----------------
__device__ __forceinline__ uint2 pack4h(float4 v) {
    __half2 h01 = __floats2half2_rn(v.x, v.y);
    __half2 h23 = __floats2half2_rn(v.z, v.w);
    uint2 r;
    r.x = *(uint32_t*)&h01;
    r.y = *(uint32_t*)&h23;
    return r;
}

// =====================================================================
// fp16 single-pass WMMA GEMM: CTA tile 256x64, 8 warps (4m x 2n) of
// warp tile 64x32 (4x2 wmma 16x16x16), KCH=16, 2-stage double buffer
// + 1-deep register prefetch, fp32 accumulate.
// =====================================================================

// ---------------- GEMM1: H = fp16(relu(X[rows] @ W1[e] + b1[e])); W1 is [k][n] ----------------
__global__ __launch_bounds__(256, 2) void wmma_gemm1(
    const float* __restrict__ x, const float* __restrict__ W1, const float* __restrict__ b1)
{
    __shared__ __align__(16) char smem[SMEM_BYTES];
    __shared__ int s_row[256];

    int m0 = blockIdx.y * 256;
    if (m0 >= g_Mtot) return;
    int e = 0;
    #pragma unroll
    for (int i = 1; i < NE; i++) if (m0 >= g_padOff[i]) e = i;
    int n0 = blockIdx.x * 64;
    int tid = threadIdx.x, wid = tid >> 5;
    int wm = wid & 3, wn = wid >> 2;

    {
        int r0 = g_assignRow[m0 + tid];
        s_row[tid] = r0 < 0 ? 0 : r0;
    }
    __syncthreads();

    const float* Wb = W1 + (size_t)e * DIM * PP;

    int arow = tid >> 2, aq = tid & 3;
    int brow = tid >> 4, bq = tid & 15;
    const float* aP[4];
    #pragma unroll
    for (int j = 0; j < 4; j++)
        aP[j] = x + (size_t)s_row[arow + 64 * j] * DIM + aq * 4;
    const float* bP = Wb + (size_t)brow * PP + n0 + bq * 4;

    float4 ra[4], rb;
    #pragma unroll
    for (int j = 0; j < 4; j++) ra[j] = *(const float4*)aP[j];
    rb = *(const float4*)bP;

    wmma::fragment<wmma::accumulator, 16, 16, 16, float> acc[4][2];
    #pragma unroll
    for (int mi = 0; mi < 4; mi++)
        #pragma unroll
        for (int ni = 0; ni < 2; ni++)
            wmma::fill_fragment(acc[mi][ni], 0.0f);

    const int NK = DIM / KCH;   // 128
    for (int k = 0; k < NK; k++) {
        int s = k & 1;
        __half* sA = (__half*)(smem + SA(s));
        __half* sB = (__half*)(smem + SB(s));

        #pragma unroll
        for (int j = 0; j < 4; j++)
            *(uint2*)&sA[(arow + 64 * j) * 24 + aq * 4] = pack4h(ra[j]);
        *(uint2*)&sB[brow * 72 + bq * 4] = pack4h(rb);
        __syncthreads();

        if (k + 1 < NK) {
            int k0 = (k + 1) * KCH;
            #pragma unroll
            for (int j = 0; j < 4; j++) ra[j] = *(const float4*)(aP[j] + k0);
            rb = *(const float4*)(bP + (size_t)k0 * PP);
        }

        wmma::fragment<wmma::matrix_a, 16, 16, 16, __half, wmma::row_major> af[4];
        wmma::fragment<wmma::matrix_b, 16, 16, 16, __half, wmma::row_major> bf[2];
        #pragma unroll
        for (int mi = 0; mi < 4; mi++)
            wmma::load_matrix_sync(af[mi], &sA[(wm * 64 + mi * 16) * 24], 24);
        #pragma unroll
        for (int ni = 0; ni < 2; ni++)
            wmma::load_matrix_sync(bf[ni], &sB[wn * 32 + ni * 16], 72);
        #pragma unroll
        for (int mi = 0; mi < 4; mi++)
            #pragma unroll
            for (int ni = 0; ni < 2; ni++)
                wmma::mma_sync(acc[mi][ni], af[mi], bf[ni], acc[mi][ni]);
    }
    __syncthreads();

    float* Cbuf = (float*)smem;
    const float* bb = b1 + e * PP;
    #pragma unroll
    for (int h = 0; h < 2; h++) {
        if ((wm >> 1) == h) {
            #pragma unroll
            for (int mi = 0; mi < 4; mi++)
                #pragma unroll
                for (int ni = 0; ni < 2; ni++)
                    wmma::store_matrix_sync(
                        &Cbuf[((wm & 1) * 64 + mi * 16) * CBUF_LD + wn * 32 + ni * 16],
                        acc[mi][ni], CBUF_LD, wmma::mem_row_major);
        }
        __syncthreads();
        #pragma unroll
        for (int j = 0; j < 16; j++) {
            int idx = tid + 256 * j;
            int r = idx >> 5, c = (idx & 31) * 2;
            int col = n0 + c;
            float v0 = fmaxf(Cbuf[r * CBUF_LD + c]     + bb[col],     0.f);
            float v1 = fmaxf(Cbuf[r * CBUF_LD + c + 1] + bb[col + 1], 0.f);
            __half2 hv = __floats2half2_rn(v0, v1);
            *(__half2*)&g_Hh[(size_t)(m0 + h * 128 + r) * PP + col] = hv;
        }
        __syncthreads();
    }
}

// ---------------- GEMM2: Yh[m] = fp16(H[m] @ W2[e]); bias/weights applied in combine ----------------
__global__ __launch_bounds__(256, 2) void wmma_gemm2(const float* __restrict__ W2)
{
    __shared__ __align__(16) char smem[SMEM_BYTES];

    int m0 = blockIdx.y * 256;
    if (m0 >= g_Mtot) return;
    int e = 0;
    #pragma unroll
    for (int i = 1; i < NE; i++) if (m0 >= g_padOff[i]) e = i;
    int n0 = blockIdx.x * 64;
    int tid = threadIdx.x, wid = tid >> 5;
    int wm = wid & 3, wn = wid >> 2;

    const float* Wb = W2 + (size_t)e * PP * DIM;

    int arow = tid >> 1, aq = tid & 1;
    int brow = tid >> 4, bq = tid & 15;
    const __half* aP0 = g_Hh + (size_t)(m0 + arow) * PP + aq * 8;
    const __half* aP1 = g_Hh + (size_t)(m0 + arow + 128) * PP + aq * 8;
    const float* bP = Wb + (size_t)brow * DIM + n0 + bq * 4;

    uint4 ra0 = *(const uint4*)aP0;
    uint4 ra1 = *(const uint4*)aP1;
    float4 rb = *(const float4*)bP;

    wmma::fragment<wmma::accumulator, 16, 16, 16, float> acc[4][2];
    #pragma unroll
    for (int mi = 0; mi < 4; mi++)
        #pragma unroll
        for (int ni = 0; ni < 2; ni++)
            wmma::fill_fragment(acc[mi][ni], 0.0f);

    const int NK = PP / KCH;    // 32
    for (int k = 0; k < NK; k++) {
        int s = k & 1;
        __half* sA = (__half*)(smem + SA(s));
        __half* sB = (__half*)(smem + SB(s));

        *(uint4*)&sA[arow * 24 + aq * 8] = ra0;
        *(uint4*)&sA[(arow + 128) * 24 + aq * 8] = ra1;
        *(uint2*)&sB[brow * 72 + bq * 4] = pack4h(rb);
        __syncthreads();

        if (k + 1 < NK) {
            int k0 = (k + 1) * KCH;
            ra0 = *(const uint4*)(aP0 + k0);
            ra1 = *(const uint4*)(aP1 + k0);
            rb  = *(const float4*)(bP + (size_t)k0 * DIM);
        }

        wmma::fragment<wmma::matrix_a, 16, 16, 16, __half, wmma::row_major> af[4];
        wmma::fragment<wmma::matrix_b, 16, 16, 16, __half, wmma::row_major> bf[2];
        #pragma unroll
        for (int mi = 0; mi < 4; mi++)
            wmma::load_matrix_sync(af[mi], &sA[(wm * 64 + mi * 16) * 24], 24);
        #pragma unroll
        for (int ni = 0; ni < 2; ni++)
            wmma::load_matrix_sync(bf[ni], &sB[wn * 32 + ni * 16], 72);
        #pragma unroll
        for (int mi = 0; mi < 4; mi++)
            #pragma unroll
            for (int ni = 0; ni < 2; ni++)
                wmma::mma_sync(acc[mi][ni], af[mi], bf[ni], acc[mi][ni]);
    }
    __syncthreads();

    float* Cbuf = (float*)smem;
    #pragma unroll
    for (int h = 0; h < 2; h++) {
        if ((wm >> 1) == h) {
            #pragma unroll
            for (int mi = 0; mi < 4; mi++)
                #pragma unroll
                for (int ni = 0; ni < 2; ni++)
                    wmma::store_matrix_sync(
                        &Cbuf[((wm & 1) * 64 + mi * 16) * CBUF_LD + wn * 32 + ni * 16],
                        acc[mi][ni], CBUF_LD, wmma::mem_row_major);
        }
        __syncthreads();
        #pragma unroll
        for (int j = 0; j < 16; j++) {
            int idx = tid + 256 * j;
            int r = idx >> 5, c = (idx & 31) * 2;
            __half2 hv = __floats2half2_rn(Cbuf[r * CBUF_LD + c], Cbuf[r * CBUF_LD + c + 1]);
            *(__half2*)&g_Yh[(size_t)(m0 + h * 128 + r) * DIM + n0 + c] = hv;
        }
        __syncthreads();
    }
}

// ---------------- combine: out[b] = w0*(Y[p0]+b2[e0]) + w1*(Y[p1]+b2[e1]) ----------------
__global__ __launch_bounds__(256) void combine_kernel(const float* __restrict__ b2,
                                                      float4* __restrict__ out4) {
    int idx = blockIdx.x * 256 + threadIdx.x;       // BATCH*DIM/4
    int b = idx >> 9;                                // DIM/4 = 512
    int c4 = idx & 511;
    int col = c4 * 4;
    float w0 = g_routeW[2 * b], w1 = g_routeW[2 * b + 1];
    int p0 = g_pos[2 * b], p1 = g_pos[2 * b + 1];
    int e0 = g_routeE[2 * b], e1 = g_routeE[2 * b + 1];
    uint2 ya = *(const uint2*)&g_Yh[(size_t)p0 * DIM + col];
    uint2 yb = *(const uint2*)&g_Yh[(size_t)p1 * DIM + col];
    __half2 a01 = *(__half2*)&ya.x, a23 = *(__half2*)&ya.y;
    __half2 b01 = *(__half2*)&yb.x, b23 = *(__half2*)&yb.y;
    float4 be0 = ((const float4*)(b2 + (size_t)e0 * DIM))[c4];
    float4 be1 = ((const float4*)(b2 + (size_t)e1 * DIM))[c4];
    float4 o;
    o.x = w0 * (__low2float(a01)  + be0.x) + w1 * (__low2float(b01)  + be1.x);
    o.y = w0 * (__high2float(a01) + be0.y) + w1 * (__high2float(b01) + be1.y);
    o.z = w0 * (__low2float(a23)  + be0.z) + w1 * (__low2float(b23)  + be1.z);
    o.w = w0 * (__high2float(a23) + be0.w) + w1 * (__high2float(b23) + be1.w);
    out4[idx] = o;
}

// ---------------- launch ----------------
extern "C" void kernel_launch(void* const* d_in, const int* in_sizes, int n_in,
                              void* d_out, int out_size)
{
    const float* x   = (const float*)d_in[0];
    const float* Wg  = (const float*)d_in[1];
    const float* bg  = (const float*)d_in[2];
    const float* Wp  = (const float*)d_in[3];
    const float* bp  = (const float*)d_in[4];
    const float* Wgg = (const float*)d_in[5];
    const float* bgg = (const float*)d_in[6];
    const float* W1  = (const float*)d_in[7];
    const float* b1  = (const float*)d_in[8];
    const float* W2  = (const float*)d_in[9];
    const float* b2  = (const float*)d_in[10];
    float* out = (float*)d_out;

    init_kernel<<<(CAP + 255) / 256, 256>>>();                   // launch 0
    route_kernel<<<BATCH, 1024>>>(x, Wg, bg, Wp, bp, Wgg, bgg);  // launch 1
    scatter_kernel<<<(BATCH + 127) / 128, 128>>>();              // launch 2
    wmma_gemm1<<<dim3(PP / 64, MT), 256>>>(x, W1, b1);           // launch 3 <- profiled slot (control)
    wmma_gemm2<<<dim3(DIM / 64, MT), 256>>>(W2);                 // launch 4
    combine_kernel<<<(BATCH * DIM / 4) / 256, 256>>>(b2, (float4*)out); // launch 5
}

// round 16
// speedup vs baseline: 3.1922x; 1.0012x over previous
#include <cuda_runtime.h>
#include <cuda_bf16.h>
#include <cuda_fp16.h>
#include <mma.h>
#include <math.h>
#include <stdint.h>

using namespace nvcuda;

// ---------------- problem constants ----------------
#define BATCH 8192
#define DIM   2048
#define NE    8
#define NG    4
#define PP    512
#define HH    192
#define CAP   18432          // 2*BATCH + 8*255 rounded up to 256-row tiles
#define MT    72             // CAP/256
#define KCH   16             // K elems per smem chunk (2-stage double buffer)

// ---------------- device scratch (~95 MB total — proven-safe) ----------------
// NOTE: __device__ globals are zero-initialized at module load. Pads in
// g_assignRow stay 0 (scatter deterministically rewrites only filled slots
// each replay); g_count/g_cursor are re-zeroed by combine_kernel at the end
// of every replay, so no init kernel is needed.
__device__ int   g_count[NE];
__device__ int   g_cursor[NE];
__device__ int   g_padOff[NE + 1];
__device__ int   g_Mtot;
__device__ int   g_routeE[2 * BATCH];
__device__ float g_routeW[2 * BATCH];
__device__ int   g_pos[2 * BATCH];
__device__ __align__(1024) int   g_assignRow[CAP];
__device__ __align__(1024) __half g_Hh[(size_t)CAP * PP];
__device__ __align__(1024) __half g_Yh[(size_t)CAP * DIM];

// ---------------- smem layout ----------------
#define SA(s)  ((s) * 12288)
#define SB(s)  (24576 + (s) * 2304)
#define CBUF_LD 68
#define SMEM_BYTES 34816

// ---------------- fast fp32-accurate cos(a)+sin(a) ----------------
__device__ __forceinline__ float cos_plus_sin(float ang) {
    double da = (double)ang;
    double kd = rint(da * 0.63661977236758138);        // 2/pi
    int q = ((int)kd) & 3;
    float r = (float)(da - kd * 1.5707963267948966);   // r in [-pi/4, pi/4]
    float r2 = r * r;
    float s = r + r * r2 * (-1.6666654611e-1f
              + r2 * (8.3321608736e-3f + r2 * (-1.9515295891e-4f)));
    float c = 1.0f + r2 * (-0.5f + r2 * (4.166664568298827e-2f
              + r2 * (-1.388731625493765e-3f + r2 * 2.443315711809948e-5f)));
    float cs = c + s, cm = c - s;
    float v = (q & 1) ? cm : cs;
    return (q & 2) ? -v : v;
}

// ---------------- routing (qm tree + selection path bit-identical) ----------------
__global__ __launch_bounds__(1024) void route_kernel(
    const float* __restrict__ x,
    const float* __restrict__ Wg, const float* __restrict__ bg,
    const float* __restrict__ Wp, const float* __restrict__ bp,
    const float* __restrict__ Wgg, const float* __restrict__ bgg)
{
    __shared__ float  warpSum[32];
    __shared__ double dWarp[32];
    __shared__ float  sh_qm;
    int b = blockIdx.x, tid = threadIdx.x;

    const float2* xr = (const float2*)(x + (size_t)b * DIM);
    float2 v = xr[tid];
    float acc = v.x + v.y;
    #pragma unroll
    for (int o = 16; o; o >>= 1) acc += __shfl_down_sync(0xffffffffu, acc, o);
    if ((tid & 31) == 0) warpSum[tid >> 5] = acc;
    __syncthreads();
    if (tid < 32) {
        float a2 = warpSum[tid];
        #pragma unroll
        for (int o = 16; o; o >>= 1) a2 += __shfl_down_sync(0xffffffffu, a2, o);
        if (tid == 0) sh_qm = a2 * (1.0f / 2048.0f);
    }
    __syncthreads();
    float qm = sh_qm;

    double tr = 0.0;
    if (tid < HH) {
        float ang = __fmul_rn(qm, (float)(7 * (tid + 1)));
        tr = (double)cos_plus_sin(ang);
    }
    #pragma unroll
    for (int o = 16; o; o >>= 1) tr += __shfl_down_sync(0xffffffffu, tr, o);
    if ((tid & 31) == 0) dWarp[tid >> 5] = tr;
    __syncthreads();

    if (tid == 0) {
        double t = 0.0;
        #pragma unroll
        for (int i = 0; i < 32; i++) t += dWarp[i];
        double m = t / 384.0;
        const double c = 0.015625;   // KTOP/D: LIF spike rate is exactly constant

        double l[NE]; double mx = -1e300;
        #pragma unroll
        for (int e = 0; e < NE; e++) {
            int g = e & (NG - 1);
            double v2 = (m * (double)Wg[e] + c * (double)Wg[NE + e] + (double)bg[e])
                      - 0.1 * (m * (double)Wp[e] + c * (double)Wp[NE + e] + (double)bp[e])
                      + (m * (double)Wgg[g] + c * (double)Wgg[NG + g] + (double)bgg[g]);
            l[e] = v2; mx = fmax(mx, v2);
        }
        int e0 = 0;
        #pragma unroll
        for (int e = 1; e < NE; e++) if (l[e] > l[e0]) e0 = e;
        int e1 = (e0 == 0) ? 1 : 0;
        #pragma unroll
        for (int e = 0; e < NE; e++) if (e != e0 && l[e] > l[e1]) e1 = e;
        float mxf = (float)mx;
        float sf[NE], Zf = 0.f;
        #pragma unroll
        for (int e = 0; e < NE; e++) { sf[e] = __expf((float)l[e] - mxf); Zf += sf[e]; }
        float s0 = sf[e0] / Zf, s1 = sf[e1] / Zf;
        float den = s0 + s1 + 1e-9f;

        g_routeE[2 * b] = e0; g_routeE[2 * b + 1] = e1;
        g_routeW[2 * b] = s0 / den; g_routeW[2 * b + 1] = s1 / den;
        atomicAdd(&g_count[e0], 1);
        atomicAdd(&g_count[e1], 1);
    }
}

// ---------------- scatter (256-aligned segments; prefix computed locally) ----------------
__global__ __launch_bounds__(128) void scatter_kernel() {
    int b = blockIdx.x * 128 + threadIdx.x;
    int off[NE + 1];
    off[0] = 0;
    #pragma unroll
    for (int e = 0; e < NE; e++)
        off[e + 1] = off[e] + ((g_count[e] + 255) & ~255);
    if (b == 0) {
        #pragma unroll
        for (int e = 0; e <= NE; e++) g_padOff[e] = off[e];
        g_Mtot = off[NE];
    }
    if (b >= BATCH) return;
    #pragma unroll
    for (int j = 0; j < 2; j++) {
        int e = g_routeE[2 * b + j];
        int pos = off[e] + atomicAdd(&g_cursor[e], 1);
        g_assignRow[pos] = b;
        g_pos[2 * b + j] = pos;
    }
}

// ---------------- helpers ----------------
__device__ __forceinline__ uint2 pack4h(float4 v) {
    __half2 h01 = __floats2half2_rn(v.x, v.y);
    __half2 h23 = __floats2half2_rn(v.z, v.w);
    uint2 r;
    r.x = *(uint32_t*)&h01;
    r.y = *(uint32_t*)&h23;
    return r;
}

// =====================================================================
// fp16 single-pass WMMA GEMM: CTA tile 256x64, 8 warps (4m x 2n) of
// warp tile 64x32 (4x2 wmma 16x16x16), KCH=16, 2-stage double buffer
// + 1-deep register prefetch, fp32 accumulate.
// =====================================================================

// ---------------- GEMM1: H = fp16(relu(X[rows] @ W1[e] + b1[e])); W1 is [k][n] ----------------
__global__ __launch_bounds__(256, 2) void wmma_gemm1(
    const float* __restrict__ x, const float* __restrict__ W1, const float* __restrict__ b1)
{
    __shared__ __align__(16) char smem[SMEM_BYTES];
    __shared__ int s_row[256];

    int m0 = blockIdx.y * 256;
    if (m0 >= g_Mtot) return;
    int e = 0;
    #pragma unroll
    for (int i = 1; i < NE; i++) if (m0 >= g_padOff[i]) e = i;
    int n0 = blockIdx.x * 64;
    int tid = threadIdx.x, wid = tid >> 5;
    int wm = wid & 3, wn = wid >> 2;

    {
        int r0 = g_assignRow[m0 + tid];
        s_row[tid] = min(max(r0, 0), BATCH - 1);   // pads (0) compute garbage, never read
    }
    __syncthreads();

    const float* Wb = W1 + (size_t)e * DIM * PP;

    int arow = tid >> 2, aq = tid & 3;
    int brow = tid >> 4, bq = tid & 15;
    const float* aP[4];
    #pragma unroll
    for (int j = 0; j < 4; j++)
        aP[j] = x + (size_t)s_row[arow + 64 * j] * DIM + aq * 4;
    const float* bP = Wb + (size_t)brow * PP + n0 + bq * 4;

    float4 ra[4], rb;
    #pragma unroll
    for (int j = 0; j < 4; j++) ra[j] = *(const float4*)aP[j];
    rb = *(const float4*)bP;

    wmma::fragment<wmma::accumulator, 16, 16, 16, float> acc[4][2];
    #pragma unroll
    for (int mi = 0; mi < 4; mi++)
        #pragma unroll
        for (int ni = 0; ni < 2; ni++)
            wmma::fill_fragment(acc[mi][ni], 0.0f);

    const int NK = DIM / KCH;   // 128
    for (int k = 0; k < NK; k++) {
        int s = k & 1;
        __half* sA = (__half*)(smem + SA(s));
        __half* sB = (__half*)(smem + SB(s));

        #pragma unroll
        for (int j = 0; j < 4; j++)
            *(uint2*)&sA[(arow + 64 * j) * 24 + aq * 4] = pack4h(ra[j]);
        *(uint2*)&sB[brow * 72 + bq * 4] = pack4h(rb);
        __syncthreads();

        if (k + 1 < NK) {
            int k0 = (k + 1) * KCH;
            #pragma unroll
            for (int j = 0; j < 4; j++) ra[j] = *(const float4*)(aP[j] + k0);
            rb = *(const float4*)(bP + (size_t)k0 * PP);
        }

        wmma::fragment<wmma::matrix_a, 16, 16, 16, __half, wmma::row_major> af[4];
        wmma::fragment<wmma::matrix_b, 16, 16, 16, __half, wmma::row_major> bf[2];
        #pragma unroll
        for (int mi = 0; mi < 4; mi++)
            wmma::load_matrix_sync(af[mi], &sA[(wm * 64 + mi * 16) * 24], 24);
        #pragma unroll
        for (int ni = 0; ni < 2; ni++)
            wmma::load_matrix_sync(bf[ni], &sB[wn * 32 + ni * 16], 72);
        #pragma unroll
        for (int mi = 0; mi < 4; mi++)
            #pragma unroll
            for (int ni = 0; ni < 2; ni++)
                wmma::mma_sync(acc[mi][ni], af[mi], bf[ni], acc[mi][ni]);
    }
    __syncthreads();

    float* Cbuf = (float*)smem;
    const float* bb = b1 + e * PP;
    #pragma unroll
    for (int h = 0; h < 2; h++) {
        if ((wm >> 1) == h) {
            #pragma unroll
            for (int mi = 0; mi < 4; mi++)
                #pragma unroll
                for (int ni = 0; ni < 2; ni++)
                    wmma::store_matrix_sync(
                        &Cbuf[((wm & 1) * 64 + mi * 16) * CBUF_LD + wn * 32 + ni * 16],
                        acc[mi][ni], CBUF_LD, wmma::mem_row_major);
        }
        __syncthreads();
        #pragma unroll
        for (int j = 0; j < 16; j++) {
            int idx = tid + 256 * j;
            int r = idx >> 5, c = (idx & 31) * 2;
            int col = n0 + c;
            float v0 = fmaxf(Cbuf[r * CBUF_LD + c]     + bb[col],     0.f);
            float v1 = fmaxf(Cbuf[r * CBUF_LD + c + 1] + bb[col + 1], 0.f);
            __half2 hv = __floats2half2_rn(v0, v1);
            *(__half2*)&g_Hh[(size_t)(m0 + h * 128 + r) * PP + col] = hv;
        }
        __syncthreads();
    }
}

// ---------------- GEMM2: Yh[m] = fp16(H[m] @ W2[e]); bias/weights applied in combine ----------------
__global__ __launch_bounds__(256, 2) void wmma_gemm2(const float* __restrict__ W2)
{
    __shared__ __align__(16) char smem[SMEM_BYTES];

    int m0 = blockIdx.y * 256;
    if (m0 >= g_Mtot) return;
    int e = 0;
    #pragma unroll
    for (int i = 1; i < NE; i++) if (m0 >= g_padOff[i]) e = i;
    int n0 = blockIdx.x * 64;
    int tid = threadIdx.x, wid = tid >> 5;
    int wm = wid & 3, wn = wid >> 2;

    const float* Wb = W2 + (size_t)e * PP * DIM;

    int arow = tid >> 1, aq = tid & 1;
    int brow = tid >> 4, bq = tid & 15;
    const __half* aP0 = g_Hh + (size_t)(m0 + arow) * PP + aq * 8;
    const __half* aP1 = g_Hh + (size_t)(m0 + arow + 128) * PP + aq * 8;
    const float* bP = Wb + (size_t)brow * DIM + n0 + bq * 4;

    uint4 ra0 = *(const uint4*)aP0;
    uint4 ra1 = *(const uint4*)aP1;
    float4 rb = *(const float4*)bP;

    wmma::fragment<wmma::accumulator, 16, 16, 16, float> acc[4][2];
    #pragma unroll
    for (int mi = 0; mi < 4; mi++)
        #pragma unroll
        for (int ni = 0; ni < 2; ni++)
            wmma::fill_fragment(acc[mi][ni], 0.0f);

    const int NK = PP / KCH;    // 32
    for (int k = 0; k < NK; k++) {
        int s = k & 1;
        __half* sA = (__half*)(smem + SA(s));
        __half* sB = (__half*)(smem + SB(s));

        *(uint4*)&sA[arow * 24 + aq * 8] = ra0;
        *(uint4*)&sA[(arow + 128) * 24 + aq * 8] = ra1;
        *(uint2*)&sB[brow * 72 + bq * 4] = pack4h(rb);
        __syncthreads();

        if (k + 1 < NK) {
            int k0 = (k + 1) * KCH;
            ra0 = *(const uint4*)(aP0 + k0);
            ra1 = *(const uint4*)(aP1 + k0);
            rb  = *(const float4*)(bP + (size_t)k0 * DIM);
        }

        wmma::fragment<wmma::matrix_a, 16, 16, 16, __half, wmma::row_major> af[4];
        wmma::fragment<wmma::matrix_b, 16, 16, 16, __half, wmma::row_major> bf[2];
        #pragma unroll
        for (int mi = 0; mi < 4; mi++)
            wmma::load_matrix_sync(af[mi], &sA[(wm * 64 + mi * 16) * 24], 24);
        #pragma unroll
        for (int ni = 0; ni < 2; ni++)
            wmma::load_matrix_sync(bf[ni], &sB[wn * 32 + ni * 16], 72);
        #pragma unroll
        for (int mi = 0; mi < 4; mi++)
            #pragma unroll
            for (int ni = 0; ni < 2; ni++)
                wmma::mma_sync(acc[mi][ni], af[mi], bf[ni], acc[mi][ni]);
    }
    __syncthreads();

    float* Cbuf = (float*)smem;
    #pragma unroll
    for (int h = 0; h < 2; h++) {
        if ((wm >> 1) == h) {
            #pragma unroll
            for (int mi = 0; mi < 4; mi++)
                #pragma unroll
                for (int ni = 0; ni < 2; ni++)
                    wmma::store_matrix_sync(
                        &Cbuf[((wm & 1) * 64 + mi * 16) * CBUF_LD + wn * 32 + ni * 16],
                        acc[mi][ni], CBUF_LD, wmma::mem_row_major);
        }
        __syncthreads();
        #pragma unroll
        for (int j = 0; j < 16; j++) {
            int idx = tid + 256 * j;
            int r = idx >> 5, c = (idx & 31) * 2;
            __half2 hv = __floats2half2_rn(Cbuf[r * CBUF_LD + c], Cbuf[r * CBUF_LD + c + 1]);
            *(__half2*)&g_Yh[(size_t)(m0 + h * 128 + r) * DIM + n0 + c] = hv;
        }
        __syncthreads();
    }
}

// ---------------- combine: out[b] = w0*(Y[p0]+b2[e0]) + w1*(Y[p1]+b2[e1]) ----------------
// Also re-zeros g_count/g_cursor for the next graph replay (replaces init_kernel).
__global__ __launch_bounds__(256) void combine_kernel(const float* __restrict__ b2,
                                                      float4* __restrict__ out4) {
    int idx = blockIdx.x * 256 + threadIdx.x;       // BATCH*DIM/4
    if (blockIdx.x == 0 && threadIdx.x < NE) {
        g_count[threadIdx.x] = 0;
        g_cursor[threadIdx.x] = 0;
    }
    int b = idx >> 9;                                // DIM/4 = 512
    int c4 = idx & 511;
    int col = c4 * 4;
    float w0 = g_routeW[2 * b], w1 = g_routeW[2 * b + 1];
    int p0 = g_pos[2 * b], p1 = g_pos[2 * b + 1];
    int e0 = g_routeE[2 * b], e1 = g_routeE[2 * b + 1];
    uint2 ya = *(const uint2*)&g_Yh[(size_t)p0 * DIM + col];
    uint2 yb = *(const uint2*)&g_Yh[(size_t)p1 * DIM + col];
    __half2 a01 = *(__half2*)&ya.x, a23 = *(__half2*)&ya.y;
    __half2 b01 = *(__half2*)&yb.x, b23 = *(__half2*)&yb.y;
    float4 be0 = ((const float4*)(b2 + (size_t)e0 * DIM))[c4];
    float4 be1 = ((const float4*)(b2 + (size_t)e1 * DIM))[c4];
    float4 o;
    o.x = w0 * (__low2float(a01)  + be0.x) + w1 * (__low2float(b01)  + be1.x);
    o.y = w0 * (__high2float(a01) + be0.y) + w1 * (__high2float(b01) + be1.y);
    o.z = w0 * (__low2float(a23)  + be0.z) + w1 * (__low2float(b23)  + be1.z);
    o.w = w0 * (__high2float(a23) + be0.w) + w1 * (__high2float(b23) + be1.w);
    out4[idx] = o;
}

// ---------------- launch ----------------
extern "C" void kernel_launch(void* const* d_in, const int* in_sizes, int n_in,
                              void* d_out, int out_size)
{
    const float* x   = (const float*)d_in[0];
    const float* Wg  = (const float*)d_in[1];
    const float* bg  = (const float*)d_in[2];
    const float* Wp  = (const float*)d_in[3];
    const float* bp  = (const float*)d_in[4];
    const float* Wgg = (const float*)d_in[5];
    const float* bgg = (const float*)d_in[6];
    const float* W1  = (const float*)d_in[7];
    const float* b1  = (const float*)d_in[8];
    const float* W2  = (const float*)d_in[9];
    const float* b2  = (const float*)d_in[10];
    float* out = (float*)d_out;

    route_kernel<<<BATCH, 1024>>>(x, Wg, bg, Wp, bp, Wgg, bgg);  // launch 0
    scatter_kernel<<<(BATCH + 127) / 128, 128>>>();              // launch 1
    wmma_gemm1<<<dim3(PP / 64, MT), 256>>>(x, W1, b1);           // launch 2
    wmma_gemm2<<<dim3(DIM / 64, MT), 256>>>(W2);                 // launch 3 <- profiled slot
    combine_kernel<<<(BATCH * DIM / 4) / 256, 256>>>(b2, (float4*)out); // launch 4
}

// round 17
// speedup vs baseline: 5.9124x; 1.8521x over previous
#include <cuda_runtime.h>
#include <cuda_bf16.h>
#include <cuda_fp16.h>
#include <mma.h>
#include <math.h>
#include <stdint.h>

using namespace nvcuda;

// ---------------- problem constants ----------------
#define BATCH 8192
#define DIM   2048
#define NE    8
#define NG    4
#define PP    512
#define HH    192
#define CAP   18432          // 2*BATCH + 8*255 rounded up to 256-row tiles
#define MT    72             // CAP/256
#define KCH   16             // K elems per smem chunk (2-stage double buffer)

// ---------------- device scratch (~95 MB total — proven-safe) ----------------
__device__ int   g_count[NE];
__device__ int   g_cursor[NE];
__device__ int   g_padOff[NE + 1];
__device__ int   g_Mtot;
__device__ int   g_routeE[2 * BATCH];
__device__ float g_routeW[2 * BATCH];
__device__ int   g_pos[2 * BATCH];
__device__ __align__(1024) int   g_assignRow[CAP];
__device__ __align__(1024) __half g_Hh[(size_t)CAP * PP];
__device__ __align__(1024) __half g_Yh[(size_t)CAP * DIM];

// ---------------- smem layout (CTA tile 256x128) ----------------
// mainloop: sA 2 x 256x24 half (12288 B), sB 2 x 16x136 half (4352 B) -> 33280 B
// epilogue (union): Cbuf 128 x 68 fp32 = 34816 B
#define SA(s)  ((s) * 12288)
#define SB(s)  (24576 + (s) * 4352)
#define CBUF_LD 68
#define SMEM_BYTES 34816

// ---------------- fast fp32-accurate cos(a)+sin(a) ----------------
__device__ __forceinline__ float cos_plus_sin(float ang) {
    double da = (double)ang;
    double kd = rint(da * 0.63661977236758138);        // 2/pi
    int q = ((int)kd) & 3;
    float r = (float)(da - kd * 1.5707963267948966);   // r in [-pi/4, pi/4]
    float r2 = r * r;
    float s = r + r * r2 * (-1.6666654611e-1f
              + r2 * (8.3321608736e-3f + r2 * (-1.9515295891e-4f)));
    float c = 1.0f + r2 * (-0.5f + r2 * (4.166664568298827e-2f
              + r2 * (-1.388731625493765e-3f + r2 * 2.443315711809948e-5f)));
    float cs = c + s, cm = c - s;
    float v = (q & 1) ? cm : cs;
    return (q & 2) ? -v : v;
}

// ---------------- routing v2: warp-per-row, all-fp32, pairwise trees ----------------
__global__ __launch_bounds__(256) void route_kernel(
    const float* __restrict__ x,
    const float* __restrict__ Wg, const float* __restrict__ bg,
    const float* __restrict__ Wp, const float* __restrict__ bp,
    const float* __restrict__ Wgg, const float* __restrict__ bgg)
{
    int w = threadIdx.x >> 5, l = threadIdx.x & 31;
    int b = blockIdx.x * 8 + w;

    // ---- qm: per-lane 16 float4 (stride 32), full pairwise tree ----
    const float4* xr = (const float4*)(x + (size_t)b * DIM);
    float s4[16];
    #pragma unroll
    for (int j = 0; j < 16; j++) {
        float4 v = xr[l + 32 * j];
        s4[j] = (v.x + v.y) + (v.z + v.w);
    }
    float p8[8], p4[4], p2[2];
    #pragma unroll
    for (int j = 0; j < 8; j++) p8[j] = s4[2 * j] + s4[2 * j + 1];
    #pragma unroll
    for (int j = 0; j < 4; j++) p4[j] = p8[2 * j] + p8[2 * j + 1];
    #pragma unroll
    for (int j = 0; j < 2; j++) p2[j] = p4[2 * j] + p4[2 * j + 1];
    float acc = p2[0] + p2[1];
    #pragma unroll
    for (int o = 16; o; o >>= 1) acc += __shfl_down_sync(0xffffffffu, acc, o);
    float qm = __shfl_sync(0xffffffffu, acc, 0) * (1.0f / 2048.0f);

    // ---- temporal mean: 6 terms per lane, pairwise ----
    float t6[6];
    #pragma unroll
    for (int j = 0; j < 6; j++) {
        int h = l * 6 + j;                 // 0..191
        float ang = __fmul_rn(qm, (float)(7 * (h + 1)));
        t6[j] = cos_plus_sin(ang);
    }
    float tr = ((t6[0] + t6[1]) + (t6[2] + t6[3])) + (t6[4] + t6[5]);
    #pragma unroll
    for (int o = 16; o; o >>= 1) tr += __shfl_down_sync(0xffffffffu, tr, o);

    if (l == 0) {
        float m = tr / 384.0f;
        const float c = 0.015625f;         // KTOP/D: LIF spike rate is exactly constant

        float lg[NE];
        #pragma unroll
        for (int e = 0; e < NE; e++) {
            int g = e & (NG - 1);
            lg[e] = (m * Wg[e] + c * Wg[NE + e] + bg[e])
                  - 0.1f * (m * Wp[e] + c * Wp[NE + e] + bp[e])
                  + (m * Wgg[g] + c * Wgg[NG + g] + bgg[g]);
        }
        int e0 = 0;
        #pragma unroll
        for (int e = 1; e < NE; e++) if (lg[e] > lg[e0]) e0 = e;
        int e1 = (e0 == 0) ? 1 : 0;
        #pragma unroll
        for (int e = 0; e < NE; e++) if (e != e0 && lg[e] > lg[e1]) e1 = e;
        float mx = lg[e0];
        float sf[NE], Zf = 0.f;
        #pragma unroll
        for (int e = 0; e < NE; e++) { sf[e] = __expf(lg[e] - mx); Zf += sf[e]; }
        float s0 = sf[e0] / Zf, s1 = sf[e1] / Zf;
        float den = s0 + s1 + 1e-9f;

        g_routeE[2 * b] = e0; g_routeE[2 * b + 1] = e1;
        g_routeW[2 * b] = s0 / den; g_routeW[2 * b + 1] = s1 / den;
        atomicAdd(&g_count[e0], 1);
        atomicAdd(&g_count[e1], 1);
    }
}

// ---------------- scatter (256-aligned segments; prefix computed locally) ----------------
__global__ __launch_bounds__(128) void scatter_kernel() {
    int b = blockIdx.x * 128 + threadIdx.x;
    int off[NE + 1];
    off[0] = 0;
    #pragma unroll
    for (int e = 0; e < NE; e++)
        off[e + 1] = off[e] + ((g_count[e] + 255) & ~255);
    if (b == 0) {
        #pragma unroll
        for (int e = 0; e <= NE; e++) g_padOff[e] = off[e];
        g_Mtot = off[NE];
    }
    if (b >= BATCH) return;
    #pragma unroll
    for (int j = 0; j < 2; j++) {
        int e = g_routeE[2 * b + j];
        int pos = off[e] + atomicAdd(&g_cursor[e], 1);
        g_assignRow[pos] = b;
        g_pos[2 * b + j] = pos;
    }
}

// ---------------- helpers ----------------
__device__ __forceinline__ uint2 pack4h(float4 v) {
    __half2 h01 = __floats2half2_rn(v.x, v.y);
    __half2 h23 = __floats2half2_rn(v.z, v.w);
    uint2 r;
    r.x = *(uint32_t*)&h01;
    r.y = *(uint32_t*)&h23;
    return r;
}

// =====================================================================
// fp16 WMMA GEMM: CTA tile 256x128, 8 warps (4m x 2n) of warp tile
// 64x64 (4x4 wmma 16x16x16), KCH=16, 2-stage double buffer + 1-deep
// register prefetch, fp32 accumulate. 1 CTA/SM (reg-heavy, L1-bound).
// =====================================================================

// ---------------- GEMM1: H = fp16(relu(X[rows] @ W1[e] + b1[e])); W1 is [k][n] ----------------
__global__ __launch_bounds__(256, 1) void wmma_gemm1(
    const float* __restrict__ x, const float* __restrict__ W1, const float* __restrict__ b1)
{
    __shared__ __align__(16) char smem[SMEM_BYTES];
    __shared__ int s_row[256];

    int m0 = blockIdx.y * 256;
    if (m0 >= g_Mtot) return;
    int e = 0;
    #pragma unroll
    for (int i = 1; i < NE; i++) if (m0 >= g_padOff[i]) e = i;
    int n0 = blockIdx.x * 128;
    int tid = threadIdx.x, wid = tid >> 5;
    int wm = wid & 3, wn = wid >> 2;

    {
        int r0 = g_assignRow[m0 + tid];
        s_row[tid] = min(max(r0, 0), BATCH - 1);
    }
    __syncthreads();

    const float* Wb = W1 + (size_t)e * DIM * PP;

    // staging: A 256x16 fp32 = 1024 float4 (4/thread); B 16x128 fp32 = 512 float4 (2/thread)
    int arow = tid >> 2, aq = tid & 3;
    const float* aP[4];
    #pragma unroll
    for (int j = 0; j < 4; j++)
        aP[j] = x + (size_t)s_row[arow + 64 * j] * DIM + aq * 4;
    int brow0 = tid >> 5, bq0 = tid & 31;   // two B float4s: rows tid>>5 and (tid>>5)+8
    const float* bP0 = Wb + (size_t)brow0 * PP + n0 + bq0 * 4;
    const float* bP1 = Wb + (size_t)(brow0 + 8) * PP + n0 + bq0 * 4;

    float4 ra[4], rb0, rb1;
    #pragma unroll
    for (int j = 0; j < 4; j++) ra[j] = *(const float4*)aP[j];
    rb0 = *(const float4*)bP0;
    rb1 = *(const float4*)bP1;

    wmma::fragment<wmma::accumulator, 16, 16, 16, float> acc[4][4];
    #pragma unroll
    for (int mi = 0; mi < 4; mi++)
        #pragma unroll
        for (int ni = 0; ni < 4; ni++)
            wmma::fill_fragment(acc[mi][ni], 0.0f);

    const int NK = DIM / KCH;   // 128
    for (int k = 0; k < NK; k++) {
        int s = k & 1;
        __half* sA = (__half*)(smem + SA(s));
        __half* sB = (__half*)(smem + SB(s));

        #pragma unroll
        for (int j = 0; j < 4; j++)
            *(uint2*)&sA[(arow + 64 * j) * 24 + aq * 4] = pack4h(ra[j]);
        *(uint2*)&sB[brow0 * 136 + bq0 * 4] = pack4h(rb0);
        *(uint2*)&sB[(brow0 + 8) * 136 + bq0 * 4] = pack4h(rb1);
        __syncthreads();

        if (k + 1 < NK) {
            int k0 = (k + 1) * KCH;
            #pragma unroll
            for (int j = 0; j < 4; j++) ra[j] = *(const float4*)(aP[j] + k0);
            rb0 = *(const float4*)(bP0 + (size_t)k0 * PP);
            rb1 = *(const float4*)(bP1 + (size_t)k0 * PP);
        }

        wmma::fragment<wmma::matrix_a, 16, 16, 16, __half, wmma::row_major> af[4];
        wmma::fragment<wmma::matrix_b, 16, 16, 16, __half, wmma::row_major> bf[4];
        #pragma unroll
        for (int mi = 0; mi < 4; mi++)
            wmma::load_matrix_sync(af[mi], &sA[(wm * 64 + mi * 16) * 24], 24);
        #pragma unroll
        for (int ni = 0; ni < 4; ni++)
            wmma::load_matrix_sync(bf[ni], &sB[wn * 64 + ni * 16], 136);
        #pragma unroll
        for (int mi = 0; mi < 4; mi++)
            #pragma unroll
            for (int ni = 0; ni < 4; ni++)
                wmma::mma_sync(acc[mi][ni], af[mi], bf[ni], acc[mi][ni]);
    }
    __syncthreads();

    // epilogue: 4 passes (m-half h, n-half g) through 128x68 fp32 Cbuf
    float* Cbuf = (float*)smem;
    const float* bb = b1 + e * PP;
    #pragma unroll
    for (int h = 0; h < 2; h++) {
        #pragma unroll
        for (int g = 0; g < 2; g++) {
            if ((wm >> 1) == h && wn == g) {
                #pragma unroll
                for (int mi = 0; mi < 4; mi++)
                    #pragma unroll
                    for (int ni = 0; ni < 4; ni++)
                        wmma::store_matrix_sync(
                            &Cbuf[((wm & 1) * 64 + mi * 16) * CBUF_LD + ni * 16],
                            acc[mi][ni], CBUF_LD, wmma::mem_row_major);
            }
            __syncthreads();
            #pragma unroll
            for (int j = 0; j < 16; j++) {
                int idx = tid + 256 * j;               // 128 rows x 32 col-pairs
                int r = idx >> 5, c = (idx & 31) * 2;
                int col = n0 + g * 64 + c;
                float v0 = fmaxf(Cbuf[r * CBUF_LD + c]     + bb[col],     0.f);
                float v1 = fmaxf(Cbuf[r * CBUF_LD + c + 1] + bb[col + 1], 0.f);
                __half2 hv = __floats2half2_rn(v0, v1);
                *(__half2*)&g_Hh[(size_t)(m0 + h * 128 + r) * PP + col] = hv;
            }
            __syncthreads();
        }
    }
}

// ---------------- GEMM2: Yh[m] = fp16(H[m] @ W2[e]); bias/weights applied in combine ----------------
__global__ __launch_bounds__(256, 1) void wmma_gemm2(const float* __restrict__ W2)
{
    __shared__ __align__(16) char smem[SMEM_BYTES];

    int m0 = blockIdx.y * 256;
    if (m0 >= g_Mtot) return;
    int e = 0;
    #pragma unroll
    for (int i = 1; i < NE; i++) if (m0 >= g_padOff[i]) e = i;
    int n0 = blockIdx.x * 128;
    int tid = threadIdx.x, wid = tid >> 5;
    int wm = wid & 3, wn = wid >> 2;

    const float* Wb = W2 + (size_t)e * PP * DIM;

    // staging: A 256x16 fp16 = 512 uint4 (2/thread); B 16x128 fp32 = 512 float4 (2/thread)
    int arow = tid >> 1, aq = tid & 1;
    const __half* aP0 = g_Hh + (size_t)(m0 + arow) * PP + aq * 8;
    const __half* aP1 = g_Hh + (size_t)(m0 + arow + 128) * PP + aq * 8;
    int brow0 = tid >> 5, bq0 = tid & 31;
    const float* bP0 = Wb + (size_t)brow0 * DIM + n0 + bq0 * 4;
    const float* bP1 = Wb + (size_t)(brow0 + 8) * DIM + n0 + bq0 * 4;

    uint4 ra0 = *(const uint4*)aP0;
    uint4 ra1 = *(const uint4*)aP1;
    float4 rb0 = *(const float4*)bP0;
    float4 rb1 = *(const float4*)bP1;

    wmma::fragment<wmma::accumulator, 16, 16, 16, float> acc[4][4];
    #pragma unroll
    for (int mi = 0; mi < 4; mi++)
        #pragma unroll
        for (int ni = 0; ni < 4; ni++)
            wmma::fill_fragment(acc[mi][ni], 0.0f);

    const int NK = PP / KCH;    // 32
    for (int k = 0; k < NK; k++) {
        int s = k & 1;
        __half* sA = (__half*)(smem + SA(s));
        __half* sB = (__half*)(smem + SB(s));

        *(uint4*)&sA[arow * 24 + aq * 8] = ra0;
        *(uint4*)&sA[(arow + 128) * 24 + aq * 8] = ra1;
        *(uint2*)&sB[brow0 * 136 + bq0 * 4] = pack4h(rb0);
        *(uint2*)&sB[(brow0 + 8) * 136 + bq0 * 4] = pack4h(rb1);
        __syncthreads();

        if (k + 1 < NK) {
            int k0 = (k + 1) * KCH;
            ra0 = *(const uint4*)(aP0 + k0);
            ra1 = *(const uint4*)(aP1 + k0);
            rb0 = *(const float4*)(bP0 + (size_t)k0 * DIM);
            rb1 = *(const float4*)(bP1 + (size_t)k0 * DIM);
        }

        wmma::fragment<wmma::matrix_a, 16, 16, 16, __half, wmma::row_major> af[4];
        wmma::fragment<wmma::matrix_b, 16, 16, 16, __half, wmma::row_major> bf[4];
        #pragma unroll
        for (int mi = 0; mi < 4; mi++)
            wmma::load_matrix_sync(af[mi], &sA[(wm * 64 + mi * 16) * 24], 24);
        #pragma unroll
        for (int ni = 0; ni < 4; ni++)
            wmma::load_matrix_sync(bf[ni], &sB[wn * 64 + ni * 16], 136);
        #pragma unroll
        for (int mi = 0; mi < 4; mi++)
            #pragma unroll
            for (int ni = 0; ni < 4; ni++)
                wmma::mma_sync(acc[mi][ni], af[mi], bf[ni], acc[mi][ni]);
    }
    __syncthreads();

    float* Cbuf = (float*)smem;
    #pragma unroll
    for (int h = 0; h < 2; h++) {
        #pragma unroll
        for (int g = 0; g < 2; g++) {
            if ((wm >> 1) == h && wn == g) {
                #pragma unroll
                for (int mi = 0; mi < 4; mi++)
                    #pragma unroll
                    for (int ni = 0; ni < 4; ni++)
                        wmma::store_matrix_sync(
                            &Cbuf[((wm & 1) * 64 + mi * 16) * CBUF_LD + ni * 16],
                            acc[mi][ni], CBUF_LD, wmma::mem_row_major);
            }
            __syncthreads();
            #pragma unroll
            for (int j = 0; j < 16; j++) {
                int idx = tid + 256 * j;
                int r = idx >> 5, c = (idx & 31) * 2;
                __half2 hv = __floats2half2_rn(Cbuf[r * CBUF_LD + c], Cbuf[r * CBUF_LD + c + 1]);
                *(__half2*)&g_Yh[(size_t)(m0 + h * 128 + r) * DIM + n0 + g * 64 + c] = hv;
            }
            __syncthreads();
        }
    }
}

// ---------------- combine: out[b] = w0*(Y[p0]+b2[e0]) + w1*(Y[p1]+b2[e1]) ----------------
__global__ __launch_bounds__(256) void combine_kernel(const float* __restrict__ b2,
                                                      float4* __restrict__ out4) {
    int idx = blockIdx.x * 256 + threadIdx.x;       // BATCH*DIM/4
    if (blockIdx.x == 0 && threadIdx.x < NE) {
        g_count[threadIdx.x] = 0;
        g_cursor[threadIdx.x] = 0;
    }
    int b = idx >> 9;                                // DIM/4 = 512
    int c4 = idx & 511;
    int col = c4 * 4;
    float w0 = g_routeW[2 * b], w1 = g_routeW[2 * b + 1];
    int p0 = g_pos[2 * b], p1 = g_pos[2 * b + 1];
    int e0 = g_routeE[2 * b], e1 = g_routeE[2 * b + 1];
    uint2 ya = *(const uint2*)&g_Yh[(size_t)p0 * DIM + col];
    uint2 yb = *(const uint2*)&g_Yh[(size_t)p1 * DIM + col];
    __half2 a01 = *(__half2*)&ya.x, a23 = *(__half2*)&ya.y;
    __half2 b01 = *(__half2*)&yb.x, b23 = *(__half2*)&yb.y;
    float4 be0 = ((const float4*)(b2 + (size_t)e0 * DIM))[c4];
    float4 be1 = ((const float4*)(b2 + (size_t)e1 * DIM))[c4];
    float4 o;
    o.x = w0 * (__low2float(a01)  + be0.x) + w1 * (__low2float(b01)  + be1.x);
    o.y = w0 * (__high2float(a01) + be0.y) + w1 * (__high2float(b01) + be1.y);
    o.z = w0 * (__low2float(a23)  + be0.z) + w1 * (__low2float(b23)  + be1.z);
    o.w = w0 * (__high2float(a23) + be0.w) + w1 * (__high2float(b23) + be1.w);
    out4[idx] = o;
}

// ---------------- launch ----------------
extern "C" void kernel_launch(void* const* d_in, const int* in_sizes, int n_in,
                              void* d_out, int out_size)
{
    const float* x   = (const float*)d_in[0];
    const float* Wg  = (const float*)d_in[1];
    const float* bg  = (const float*)d_in[2];
    const float* Wp  = (const float*)d_in[3];
    const float* bp  = (const float*)d_in[4];
    const float* Wgg = (const float*)d_in[5];
    const float* bgg = (const float*)d_in[6];
    const float* W1  = (const float*)d_in[7];
    const float* b1  = (const float*)d_in[8];
    const float* W2  = (const float*)d_in[9];
    const float* b2  = (const float*)d_in[10];
    float* out = (float*)d_out;

    route_kernel<<<BATCH / 8, 256>>>(x, Wg, bg, Wp, bp, Wgg, bgg);   // launch 0
    scatter_kernel<<<(BATCH + 127) / 128, 128>>>();                  // launch 1
    wmma_gemm1<<<dim3(PP / 128, MT), 256>>>(x, W1, b1);              // launch 2
    wmma_gemm2<<<dim3(DIM / 128, MT), 256>>>(W2);                    // launch 3 <- profiled slot
    combine_kernel<<<(BATCH * DIM / 4) / 256, 256>>>(b2, (float4*)out); // launch 4
}